// round 1
// baseline (speedup 1.0000x reference)
#include <cuda_runtime.h>

// DCNv2 forward, fp32 baseline.
// B=4, Cin=Cout=256, H=W=64, DG=2, K=3x3=9, CG=128.

#define BATCH 4
#define CIN   256
#define COUT  256
#define Hdim  64
#define Wdim  64
#define DGRP  2
#define KTAP  9
#define CG    128
#define OMC   54                 // 3*DG*K offset/mask channels
#define HW    (Hdim * Wdim)      // 4096
#define KDIM  (DGRP * CG * KTAP) // 2304

// ---------------- scratch (static device allocations; no cudaMalloc) -------
__device__ float  g_om[BATCH * OMC * HW];        // offset-conv output
__device__ float  g_wr[KDIM * COUT];             // weight repacked [kk][oc]
__device__ float  g_woffr[KTAP * CIN * OMC];     // w_off repacked [k][c][oc]
__device__ float4 g_pw[BATCH * DGRP * KTAP * HW];// 4 bilinear weights (mask-premul)
__device__ int4   g_pi[BATCH * DGRP * KTAP * HW];// 4 clamped spatial offsets

// ---------------- K0: repack weights ---------------------------------------
__global__ void k_rearrange(const float* __restrict__ weight,
                            const float* __restrict__ w_off) {
    int i = blockIdx.x * blockDim.x + threadIdx.x;
    if (i < KDIM * COUT) {
        int kk = i >> 8;            // /256
        int oc = i & 255;
        int dg  = kk / (KTAP * CG);
        int rem = kk % (KTAP * CG);
        int k   = rem / CG;
        int c   = rem % CG;
        g_wr[i] = weight[(oc * CIN + dg * CG + c) * KTAP + k];
    }
    if (i < KTAP * CIN * OMC) {
        int oc = i % OMC;
        int t  = i / OMC;
        int c  = t % CIN;
        int k  = t / CIN;
        g_woffr[i] = w_off[(oc * CIN + c) * KTAP + k];
    }
}

// ---------------- K1: offset-predicting 3x3 conv (im2col GEMM) -------------
// grid (H, B); block 256. C-tile: 54 oc x 64 w.
__global__ __launch_bounds__(256) void k_offconv(const float* __restrict__ x,
                                                 const float* __restrict__ b_off) {
    __shared__ float As[32 * OMC + 8];   // [cl][oc], slack for oc>=54 reads
    __shared__ float Bs[32 * Wdim];      // [cl][w]
    const int b = blockIdx.y, h = blockIdx.x;
    const int tid = threadIdx.x;
    const int w = tid & 63, q = tid >> 6;   // thread handles oc = q + 4j

    float acc[14];
#pragma unroll
    for (int j = 0; j < 14; j++) acc[j] = 0.f;

    const float* xb = x + (size_t)b * CIN * HW;

    for (int k = 0; k < KTAP; k++) {
        const int ky = k / 3, kx = k % 3;
        const int gy = h + ky - 1;
        const bool rowok = (gy >= 0) && (gy < Hdim);
        for (int c0 = 0; c0 < CIN; c0 += 32) {
            for (int i = tid; i < 32 * OMC; i += 256)
                As[i] = g_woffr[(k * CIN + c0) * OMC + i];
            for (int i = tid; i < 32 * Wdim; i += 256) {
                int cl = i >> 6, wc = i & 63;
                int gx = wc + kx - 1;
                float v = 0.f;
                if (rowok && gx >= 0 && gx < Wdim)
                    v = xb[(c0 + cl) * HW + gy * Wdim + gx];
                Bs[i] = v;
            }
            __syncthreads();
#pragma unroll 8
            for (int cl = 0; cl < 32; cl++) {
                float xv = Bs[cl * 64 + w];
#pragma unroll
                for (int j = 0; j < 14; j++)
                    acc[j] += As[cl * OMC + (q + 4 * j)] * xv;
            }
            __syncthreads();
        }
    }
#pragma unroll
    for (int j = 0; j < 14; j++) {
        int oc = q + 4 * j;
        if (oc < OMC)
            g_om[((b * OMC + oc) * Hdim + h) * Wdim + w] = acc[j] + b_off[oc];
    }
}

// ---------------- K2: offsets -> bilinear params ----------------------------
__global__ void k_params() {
    int i = blockIdx.x * blockDim.x + threadIdx.x;
    // decode (b, dg, k, h, w)
    int w = i & 63;  int t = i >> 6;
    int h = t & 63;  t >>= 6;
    int k = t % KTAP; t /= KTAP;
    int dg = t % DGRP;
    int b  = t / DGRP;

    const float* om = g_om + (size_t)b * OMC * HW;
    int sp = h * Wdim + w;
    float oy = om[(dg * 18 + k) * HW + sp];
    float ox = om[(dg * 18 + 9 + k) * HW + sp];
    float mr = om[(36 + dg * 9 + k) * HW + sp];
    float m  = 1.f / (1.f + expf(-mr));

    int ky = k / 3, kx = k % 3;
    float py = oy + (float)(h + ky - 1);
    float px = ox + (float)(w + kx - 1);
    float y0f = floorf(py), x0f = floorf(px);
    float wy1 = py - y0f, wx1 = px - x0f;
    float wy0 = 1.f - wy1, wx0 = 1.f - wx1;
    int y0 = (int)y0f, x0 = (int)x0f;
    int y1 = y0 + 1,   x1 = x0 + 1;
    float fy0 = (y0 >= 0 && y0 < Hdim) ? 1.f : 0.f;
    float fy1 = (y1 >= 0 && y1 < Hdim) ? 1.f : 0.f;
    float fx0 = (x0 >= 0 && x0 < Wdim) ? 1.f : 0.f;
    float fx1 = (x1 >= 0 && x1 < Wdim) ? 1.f : 0.f;
    int iy0 = min(max(y0, 0), Hdim - 1) * Wdim;
    int iy1 = min(max(y1, 0), Hdim - 1) * Wdim;
    int ix0 = min(max(x0, 0), Wdim - 1);
    int ix1 = min(max(x1, 0), Wdim - 1);

    g_pw[i] = make_float4(wy0 * wx0 * m * fy0 * fx0,
                          wy0 * wx1 * m * fy0 * fx1,
                          wy1 * wx0 * m * fy1 * fx0,
                          wy1 * wx1 * m * fy1 * fx1);
    g_pi[i] = make_int4(iy0 + ix0, iy0 + ix1, iy1 + ix0, iy1 + ix1);
}

// ---------------- K3: fused sampling + grouped GEMM -------------------------
// grid (H, B); block 256. C-tile 256 oc x 64 w, 8x8 per thread.
__global__ __launch_bounds__(256, 2) void k_main(const float* __restrict__ x,
                                                 const float* __restrict__ bias,
                                                 float* __restrict__ out) {
    __shared__ float As[32 * COUT];  // 32 KB  [cl][oc]
    __shared__ float Bs[32 * Wdim];  //  8 KB  [cl][w]
    const int b = blockIdx.y, h = blockIdx.x;
    const int tid = threadIdx.x;
    const int wi = tid & 7;          // w octet:  w in [wi*8, wi*8+8)
    const int oi = tid >> 3;         // oc octet: oc in [oi*8, oi*8+8)
    const int wcol = tid & 63, cq = tid >> 6;  // B-tile build mapping

    float acc[8][8];
#pragma unroll
    for (int r = 0; r < 8; r++)
#pragma unroll
        for (int s = 0; s < 8; s++) acc[r][s] = 0.f;

    const float* xg = x + (size_t)b * CIN * HW;

    for (int dg = 0; dg < DGRP; dg++) {
        for (int k = 0; k < KTAP; k++) {
            const int pidx = (((b * DGRP + dg) * KTAP + k) * Hdim + h) * Wdim + wcol;
            const float4 pw = g_pw[pidx];
            const int4   pi = g_pi[pidx];
            for (int c0 = 0; c0 < CG; c0 += 32) {
                const int kkbase = (dg * KTAP + k) * CG + c0;
                // A tile: 32x256 contiguous floats, float4 coalesced
                {
                    const float4* src = (const float4*)(g_wr + (size_t)kkbase * COUT);
                    float4* dst = (float4*)As;
#pragma unroll
                    for (int i = 0; i < 8; i++)
                        dst[tid + i * 256] = src[tid + i * 256];
                }
                // B tile: bilinear sample on the fly (4 gathers/elem)
#pragma unroll
                for (int j = 0; j < 8; j++) {
                    int cl = cq + 4 * j;
                    const float* xb = xg + (size_t)(dg * CG + c0 + cl) * HW;
                    Bs[cl * 64 + wcol] = pw.x * xb[pi.x] + pw.y * xb[pi.y]
                                       + pw.z * xb[pi.z] + pw.w * xb[pi.w];
                }
                __syncthreads();
#pragma unroll
                for (int cl = 0; cl < 32; cl++) {
                    float4 a0 = *(const float4*)&As[cl * COUT + oi * 8];
                    float4 a1 = *(const float4*)&As[cl * COUT + oi * 8 + 4];
                    float4 b0 = *(const float4*)&Bs[cl * 64 + wi * 8];
                    float4 b1 = *(const float4*)&Bs[cl * 64 + wi * 8 + 4];
                    float av[8] = {a0.x, a0.y, a0.z, a0.w, a1.x, a1.y, a1.z, a1.w};
                    float bv[8] = {b0.x, b0.y, b0.z, b0.w, b1.x, b1.y, b1.z, b1.w};
#pragma unroll
                    for (int r = 0; r < 8; r++)
#pragma unroll
                        for (int s = 0; s < 8; s++)
                            acc[r][s] += av[r] * bv[s];
                }
                __syncthreads();
            }
        }
    }
    // epilogue
#pragma unroll
    for (int r = 0; r < 8; r++) {
        int oc = oi * 8 + r;
        float bv = bias[oc];
        float* op = out + (((size_t)b * COUT + oc) * Hdim + h) * Wdim + wi * 8;
#pragma unroll
        for (int s = 0; s < 8; s++) op[s] = acc[r][s] + bv;
    }
}

// ---------------- launch ----------------------------------------------------
extern "C" void kernel_launch(void* const* d_in, const int* in_sizes, int n_in,
                              void* d_out, int out_size) {
    const float* x      = (const float*)d_in[0];
    const float* w_off  = (const float*)d_in[1];
    const float* b_off  = (const float*)d_in[2];
    const float* weight = (const float*)d_in[3];
    const float* bias   = (const float*)d_in[4];
    float* out = (float*)d_out;

    k_rearrange<<<(KDIM * COUT + 255) / 256, 256>>>(weight, w_off);
    dim3 gbh(Hdim, BATCH);
    k_offconv<<<gbh, 256>>>(x, b_off);
    k_params<<<(BATCH * DGRP * KTAP * HW) / 256, 256>>>();
    k_main<<<gbh, 256>>>(x, bias, out);
}

// round 4
// speedup vs baseline: 1.9200x; 1.9200x over previous
#include <cuda_runtime.h>
#include <cstdint>

// DCNv2 forward on GB300 via legacy mma.sync tf32 (compute_103-safe).
// B=4, Cin=Cout=256, H=W=64, DG=2, K=3x3. KTOT=2304, NCOL=16384.

#define BATCH 4
#define CIN   256
#define COUT  256
#define Hdim  64
#define Wdim  64
#define HW    4096
#define KTOT  2304
#define NCOL  16384
#define NCHUNK 72                 // K chunks of 32

// ---------------- device scratch (no cudaMalloc) ----------------------------
__device__ float  g_xt[BATCH * HW * CIN];     // x transposed [b][pos][c] 16 MB
__device__ float  g_wrf[NCHUNK * 8192];       // main A, fragment-packed
__device__ float  g_wofff[NCHUNK * 2048];     // offset A (M pad 64), frag-packed
__device__ float  g_om2[54 * NCOL];           // offset conv out [ch][pos]
__device__ float4 g_pw[BATCH * 2 * 9 * HW];   // bilinear weights (mask premul)
__device__ int4   g_pi[BATCH * 2 * 9 * HW];   // bilinear corner offsets

// ---------------- helpers ---------------------------------------------------
__device__ __forceinline__ float to_tf32(float f) {
    uint32_t b;
    asm("cvt.rna.tf32.f32 %0, %1;" : "=r"(b) : "f"(f));
    return __uint_as_float(b);
}
__device__ __forceinline__ float4 tf4(float4 v) {
    return make_float4(to_tf32(v.x), to_tf32(v.y), to_tf32(v.z), to_tf32(v.w));
}
__device__ __forceinline__ void mma_tf32(float* d, const uint32_t* a, const uint32_t* b) {
    asm volatile(
        "mma.sync.aligned.m16n8k8.row.col.f32.tf32.tf32.f32 "
        "{%0,%1,%2,%3}, {%4,%5,%6,%7}, {%8,%9}, {%0,%1,%2,%3};"
        : "+f"(d[0]), "+f"(d[1]), "+f"(d[2]), "+f"(d[3])
        : "r"(a[0]), "r"(a[1]), "r"(a[2]), "r"(a[3]), "r"(b[0]), "r"(b[1]));
}

// ---------------- K0: fragment-pack weights ---------------------------------
// A fragment (m16n8k8.tf32, row): a_r holds A[mt*16 + (lane>>2) + 8*(r&1)]
//                                  [klocal = (lane&3) + 4*(r>>1)]
// layout: [chunk][s(4)][mt][lane(32)][r(4)]  (main mt=16, off mt=4)
__global__ void k_repack(const float* __restrict__ weight,
                         const float* __restrict__ w_off) {
    int i = blockIdx.x * blockDim.x + threadIdx.x;
    if (i < NCHUNK * 8192) {
        int c = i >> 13, r2 = i & 8191;
        int s = r2 >> 11, mt = (r2 >> 7) & 15, lane = (r2 >> 2) & 31, r = r2 & 3;
        int oc = mt * 16 + (lane >> 2) + 8 * (r & 1);
        int kk = c * 32 + s * 8 + (lane & 3) + 4 * (r >> 1);
        int dg = kk / 1152, km = (kk >> 7) % 9, cc = kk & 127;
        g_wrf[i] = to_tf32(weight[(oc * CIN + dg * 128 + cc) * 9 + km]);
    }
    if (i < NCHUNK * 2048) {
        int c = i >> 11, r2 = i & 2047;
        int s = r2 >> 9, mt = (r2 >> 7) & 3, lane = (r2 >> 2) & 31, r = r2 & 3;
        int oc = mt * 16 + (lane >> 2) + 8 * (r & 1);
        int kk = c * 32 + s * 8 + (lane & 3) + 4 * (r >> 1);
        int k9 = kk >> 8, cc = kk & 255;
        g_wofff[i] = (oc < 54) ? to_tf32(w_off[(oc * CIN + cc) * 9 + k9]) : 0.f;
    }
}

// ---------------- K1: transpose x -> [b][pos][c] ----------------------------
__global__ void k_transpose(const float* __restrict__ x) {
    __shared__ float t[32][33];
    int b = blockIdx.z;
    int p0 = blockIdx.x * 32, c0 = blockIdx.y * 32;
    int tx = threadIdx.x, ty = threadIdx.y;
#pragma unroll
    for (int j = 0; j < 32; j += 8)
        t[ty + j][tx] = x[((size_t)b * CIN + c0 + ty + j) * HW + p0 + tx];
    __syncthreads();
#pragma unroll
    for (int j = 0; j < 32; j += 8)
        g_xt[((size_t)b * HW + p0 + ty + j) * CIN + c0 + tx] = t[tx][ty + j];
}

// B-tile smem layout: Bs[s(4)][w(64)][8] with inner = (klocal&3)*2 + (klocal>>2)
// fragment read: v2 at Bs[s][nt*8 + (lane>>2)][(lane&3)*2]  (conflict-free)

// ---------------- K2: offset-conv GEMM (M=64 pad, im2col fused) -------------
__global__ __launch_bounds__(256, 2) void k_offgemm(const float* __restrict__ b_off) {
    __shared__ float As[2048];
    __shared__ float Bs[2048];
    const int tid = threadIdx.x, lane = tid & 31, wid = tid >> 5;
    const int b = blockIdx.x >> 6, h = blockIdx.x & 63;
    const int warp_m = wid & 1, warp_n = wid >> 1;
    const int wq = tid >> 2, q = tid & 3;

    float acc[2][2][4];
#pragma unroll
    for (int i = 0; i < 2; i++)
#pragma unroll
        for (int t = 0; t < 2; t++)
#pragma unroll
            for (int r = 0; r < 4; r++) acc[i][t][r] = 0.f;

    for (int c = 0; c < NCHUNK; c++) {
        __syncthreads();
        {   // A copy: 2048 floats, 512 float4
            const float4* src = (const float4*)(g_wofff + c * 2048);
            float4* dst = (float4*)As;
            dst[tid] = src[tid];
            dst[tid + 256] = src[tid + 256];
        }
        {   // B build: im2col from g_xt
            int k9 = c >> 3, cb = (c & 7) * 32;
            int gy = h + k9 / 3 - 1, gx = wq + k9 % 3 - 1;
            float4 v0 = make_float4(0, 0, 0, 0), v1 = v0;
            if (gy >= 0 && gy < Hdim && gx >= 0 && gx < Wdim) {
                const float4* src = (const float4*)(g_xt +
                    ((size_t)(b * HW + gy * 64 + gx)) * 256 + cb + q * 8);
                v0 = tf4(src[0]); v1 = tf4(src[1]);
            }
            float* bs = Bs + q * 512 + wq * 8;
            bs[0] = v0.x; bs[2] = v0.y; bs[4] = v0.z; bs[6] = v0.w;
            bs[1] = v1.x; bs[3] = v1.y; bs[5] = v1.z; bs[7] = v1.w;
        }
        __syncthreads();
#pragma unroll
        for (int s = 0; s < 4; s++) {
            uint32_t af[2][4], bf[2][2];
#pragma unroll
            for (int i = 0; i < 2; i++) {
                const uint32_t* p = (const uint32_t*)&As[((s * 4 + warp_m * 2 + i) * 32 + lane) * 4];
                af[i][0] = p[0]; af[i][1] = p[1]; af[i][2] = p[2]; af[i][3] = p[3];
            }
#pragma unroll
            for (int t = 0; t < 2; t++) {
                int nt = warp_n * 2 + t;
                const uint32_t* p = (const uint32_t*)&Bs[s * 512 + (nt * 8 + (lane >> 2)) * 8 + (lane & 3) * 2];
                bf[t][0] = p[0]; bf[t][1] = p[1];
            }
#pragma unroll
            for (int i = 0; i < 2; i++)
#pragma unroll
                for (int t = 0; t < 2; t++)
                    mma_tf32(acc[i][t], af[i], bf[t]);
        }
    }
    // epilogue -> g_om2[ch][pos] (+b_off), ch<54
#pragma unroll
    for (int i = 0; i < 2; i++) {
        int ch0 = (warp_m * 2 + i) * 16 + (lane >> 2);
#pragma unroll
        for (int t = 0; t < 2; t++) {
            int wcol = (warp_n * 2 + t) * 8 + (lane & 3) * 2;
            int pos = b * HW + h * 64 + wcol;
            if (ch0 < 54) {
                float bv = b_off[ch0];
                *(float2*)&g_om2[(size_t)ch0 * NCOL + pos] =
                    make_float2(acc[i][t][0] + bv, acc[i][t][1] + bv);
            }
            if (ch0 + 8 < 54) {
                float bv = b_off[ch0 + 8];
                *(float2*)&g_om2[(size_t)(ch0 + 8) * NCOL + pos] =
                    make_float2(acc[i][t][2] + bv, acc[i][t][3] + bv);
            }
        }
    }
}

// ---------------- K3: offsets -> bilinear params ----------------------------
__global__ void k_params() {
    int i = blockIdx.x * blockDim.x + threadIdx.x;   // ((b*2+dg)*9+k)*HW + sp
    int sp = i & 4095;
    int t = i >> 12;
    int k = t % 9; t /= 9;
    int dg = t & 1, b = t >> 1;
    int h = sp >> 6, w = sp & 63;
    int pos = b * HW + sp;

    float oy = g_om2[(size_t)(dg * 18 + k) * NCOL + pos];
    float ox = g_om2[(size_t)(dg * 18 + 9 + k) * NCOL + pos];
    float mr = g_om2[(size_t)(36 + dg * 9 + k) * NCOL + pos];
    float m = 1.f / (1.f + expf(-mr));

    float py = oy + (float)(h + k / 3 - 1);
    float px = ox + (float)(w + k % 3 - 1);
    float y0f = floorf(py), x0f = floorf(px);
    float wy1 = py - y0f, wx1 = px - x0f;
    float wy0 = 1.f - wy1, wx0 = 1.f - wx1;
    int y0 = (int)y0f, x0 = (int)x0f;
    int y1 = y0 + 1, x1 = x0 + 1;
    float fy0 = (y0 >= 0 && y0 < Hdim) ? 1.f : 0.f;
    float fy1 = (y1 >= 0 && y1 < Hdim) ? 1.f : 0.f;
    float fx0 = (x0 >= 0 && x0 < Wdim) ? 1.f : 0.f;
    float fx1 = (x1 >= 0 && x1 < Wdim) ? 1.f : 0.f;
    int iy0 = min(max(y0, 0), Hdim - 1) * Wdim;
    int iy1 = min(max(y1, 0), Hdim - 1) * Wdim;
    int ix0 = min(max(x0, 0), Wdim - 1);
    int ix1 = min(max(x1, 0), Wdim - 1);

    g_pw[i] = make_float4(wy0 * wx0 * m * fy0 * fx0, wy0 * wx1 * m * fy0 * fx1,
                          wy1 * wx0 * m * fy1 * fx0, wy1 * wx1 * m * fy1 * fx1);
    g_pi[i] = make_int4(iy0 + ix0, iy0 + ix1, iy1 + ix0, iy1 + ix1);
}

// ---------------- K4: main GEMM (M=256), bilinear sampling fused ------------
__global__ __launch_bounds__(256, 2) void k_maingemm(const float* __restrict__ bias,
                                                     float* __restrict__ outp) {
    __shared__ float As[8192];   // 32 KB
    __shared__ float Bs[2048];   //  8 KB
    const int tid = threadIdx.x, lane = tid & 31, wid = tid >> 5;
    const int b = blockIdx.x >> 6, h = blockIdx.x & 63;
    const int warp_m = wid & 3, warp_n = wid >> 2;
    const int wq = tid >> 2, q = tid & 3;

    float acc[4][4][4];
#pragma unroll
    for (int i = 0; i < 4; i++)
#pragma unroll
        for (int t = 0; t < 4; t++)
#pragma unroll
            for (int r = 0; r < 4; r++) acc[i][t][r] = 0.f;

    for (int c = 0; c < NCHUNK; c++) {
        __syncthreads();
        {   // A copy: 8192 floats, 2048 float4
            const float4* src = (const float4*)(g_wrf + (size_t)c * 8192);
            float4* dst = (float4*)As;
#pragma unroll
            for (int i = 0; i < 8; i++)
                dst[tid + i * 256] = src[tid + i * 256];
        }
        {   // B build: bilinear sample 32 channels x 64 cols
            int dg = c / 36, km = (c % 36) >> 2, cb = (c & 3) * 32;
            int task = ((b * 2 + dg) * 9 + km) * HW + h * 64 + wq;
            float4 pw = g_pw[task];
            int4 pi = g_pi[task];
            const float* xb = g_xt + ((size_t)b * HW) * 256 + dg * 128 + cb + q * 8;
            const float4* s0 = (const float4*)(xb + (size_t)pi.x * 256);
            const float4* s1 = (const float4*)(xb + (size_t)pi.y * 256);
            const float4* s2 = (const float4*)(xb + (size_t)pi.z * 256);
            const float4* s3 = (const float4*)(xb + (size_t)pi.w * 256);
            float4 a0 = s0[0], b0 = s1[0], c0 = s2[0], d0 = s3[0];
            float4 a1 = s0[1], b1 = s1[1], c1 = s2[1], d1 = s3[1];
            float4 v0 = tf4(make_float4(
                pw.x * a0.x + pw.y * b0.x + pw.z * c0.x + pw.w * d0.x,
                pw.x * a0.y + pw.y * b0.y + pw.z * c0.y + pw.w * d0.y,
                pw.x * a0.z + pw.y * b0.z + pw.z * c0.z + pw.w * d0.z,
                pw.x * a0.w + pw.y * b0.w + pw.z * c0.w + pw.w * d0.w));
            float4 v1 = tf4(make_float4(
                pw.x * a1.x + pw.y * b1.x + pw.z * c1.x + pw.w * d1.x,
                pw.x * a1.y + pw.y * b1.y + pw.z * c1.y + pw.w * d1.y,
                pw.x * a1.z + pw.y * b1.z + pw.z * c1.z + pw.w * d1.z,
                pw.x * a1.w + pw.y * b1.w + pw.z * c1.w + pw.w * d1.w));
            float* bs = Bs + q * 512 + wq * 8;
            bs[0] = v0.x; bs[2] = v0.y; bs[4] = v0.z; bs[6] = v0.w;
            bs[1] = v1.x; bs[3] = v1.y; bs[5] = v1.z; bs[7] = v1.w;
        }
        __syncthreads();
#pragma unroll
        for (int s = 0; s < 4; s++) {
            uint32_t af[4][4], bf[4][2];
#pragma unroll
            for (int i = 0; i < 4; i++) {
                const uint32_t* p = (const uint32_t*)&As[((s * 16 + warp_m * 4 + i) * 32 + lane) * 4];
                af[i][0] = p[0]; af[i][1] = p[1]; af[i][2] = p[2]; af[i][3] = p[3];
            }
#pragma unroll
            for (int t = 0; t < 4; t++) {
                int nt = warp_n * 4 + t;
                const uint32_t* p = (const uint32_t*)&Bs[s * 512 + (nt * 8 + (lane >> 2)) * 8 + (lane & 3) * 2];
                bf[t][0] = p[0]; bf[t][1] = p[1];
            }
#pragma unroll
            for (int i = 0; i < 4; i++)
#pragma unroll
                for (int t = 0; t < 4; t++)
                    mma_tf32(acc[i][t], af[i], bf[t]);
        }
    }
    // epilogue -> out[b][oc][h][w] (+bias)
#pragma unroll
    for (int i = 0; i < 4; i++) {
        int oc0 = (warp_m * 4 + i) * 16 + (lane >> 2);
        float bv0 = bias[oc0], bv8 = bias[oc0 + 8];
#pragma unroll
        for (int t = 0; t < 4; t++) {
            int wcol = (warp_n * 4 + t) * 8 + (lane & 3) * 2;
            size_t base = ((size_t)(b * 256 + oc0)) * HW + h * 64 + wcol;
            *(float2*)&outp[base] = make_float2(acc[i][t][0] + bv0, acc[i][t][1] + bv0);
            *(float2*)&outp[base + 8 * HW] = make_float2(acc[i][t][2] + bv8, acc[i][t][3] + bv8);
        }
    }
}

// ---------------- launch ----------------------------------------------------
extern "C" void kernel_launch(void* const* d_in, const int* in_sizes, int n_in,
                              void* d_out, int out_size) {
    const float* x      = (const float*)d_in[0];
    const float* w_off  = (const float*)d_in[1];
    const float* b_off  = (const float*)d_in[2];
    const float* weight = (const float*)d_in[3];
    const float* bias   = (const float*)d_in[4];
    float* out = (float*)d_out;

    k_repack<<<(NCHUNK * 8192 + 255) / 256, 256>>>(weight, w_off);
    k_transpose<<<dim3(HW / 32, CIN / 32, BATCH), dim3(32, 8)>>>(x);
    k_offgemm<<<256, 256>>>(b_off);
    k_params<<<BATCH * 2 * 9 * HW / 256, 256>>>();
    k_maingemm<<<256, 256>>>(bias, out);
}

// round 6
// speedup vs baseline: 2.2719x; 1.1832x over previous
#include <cuda_runtime.h>
#include <cstdint>

// DCNv2 forward on GB300 via mma.sync tf32, software-pipelined (compute_103-safe).
// B=4, Cin=Cout=256, H=W=64, DG=2, K=3x3. KTOT=2304, NCOL=16384.

#define BATCH 4
#define CIN   256
#define COUT  256
#define Hdim  64
#define Wdim  64
#define HW    4096
#define KTOT  2304
#define NCOL  16384
#define NCHUNK 72                 // K chunks of 32

// ---------------- device scratch (no cudaMalloc) ----------------------------
__device__ float  g_xt[BATCH * HW * CIN];     // x transposed [b][pos][c] 16 MB
__device__ float  g_wrf[NCHUNK * 8192];       // main A, fragment-packed
__device__ float  g_wofff[NCHUNK * 2048];     // offset A (M pad 64), frag-packed
__device__ float  g_om2[54 * NCOL];           // offset conv out [ch][pos]
__device__ float4 g_pw[BATCH * 2 * 9 * HW];   // bilinear weights (mask premul)
__device__ int4   g_pi[BATCH * 2 * 9 * HW];   // bilinear corner offsets

// ---------------- helpers ---------------------------------------------------
__device__ __forceinline__ float to_tf32(float f) {
    uint32_t b;
    asm("cvt.rna.tf32.f32 %0, %1;" : "=r"(b) : "f"(f));
    return __uint_as_float(b);
}
__device__ __forceinline__ float4 tf4(float4 v) {
    return make_float4(to_tf32(v.x), to_tf32(v.y), to_tf32(v.z), to_tf32(v.w));
}
__device__ __forceinline__ void mma_tf32(float* d, const uint32_t* a, const uint32_t* b) {
    asm volatile(
        "mma.sync.aligned.m16n8k8.row.col.f32.tf32.tf32.f32 "
        "{%0,%1,%2,%3}, {%4,%5,%6,%7}, {%8,%9}, {%0,%1,%2,%3};"
        : "+f"(d[0]), "+f"(d[1]), "+f"(d[2]), "+f"(d[3])
        : "r"(a[0]), "r"(a[1]), "r"(a[2]), "r"(a[3]), "r"(b[0]), "r"(b[1]));
}
#define CP_ASYNC16(sa, gp) \
    asm volatile("cp.async.cg.shared.global [%0], [%1], 16;" :: "r"(sa), "l"(gp))
#define CP_COMMIT() asm volatile("cp.async.commit_group;" ::: "memory")
#define CP_WAIT0()  asm volatile("cp.async.wait_group 0;" ::: "memory")

// ---------------- K0: fragment-pack weights ---------------------------------
// A fragment (m16n8k8.tf32, row): a_r holds A[mt*16 + (lane>>2) + 8*(r&1)]
//                                  [klocal = (lane&3) + 4*(r>>1)]
__global__ void k_repack(const float* __restrict__ weight,
                         const float* __restrict__ w_off) {
    int i = blockIdx.x * blockDim.x + threadIdx.x;
    if (i < NCHUNK * 8192) {
        int c = i >> 13, r2 = i & 8191;
        int s = r2 >> 11, mt = (r2 >> 7) & 15, lane = (r2 >> 2) & 31, r = r2 & 3;
        int oc = mt * 16 + (lane >> 2) + 8 * (r & 1);
        int kk = c * 32 + s * 8 + (lane & 3) + 4 * (r >> 1);
        int dg = kk / 1152, km = (kk >> 7) % 9, cc = kk & 127;
        g_wrf[i] = to_tf32(weight[(oc * CIN + dg * 128 + cc) * 9 + km]);
    }
    if (i < NCHUNK * 2048) {
        int c = i >> 11, r2 = i & 2047;
        int s = r2 >> 9, mt = (r2 >> 7) & 3, lane = (r2 >> 2) & 31, r = r2 & 3;
        int oc = mt * 16 + (lane >> 2) + 8 * (r & 1);
        int kk = c * 32 + s * 8 + (lane & 3) + 4 * (r >> 1);
        int k9 = kk >> 8, cc = kk & 255;
        g_wofff[i] = (oc < 54) ? to_tf32(w_off[(oc * CIN + cc) * 9 + k9]) : 0.f;
    }
}

// ---------------- K1: transpose x -> [b][pos][c] ----------------------------
__global__ void k_transpose(const float* __restrict__ x) {
    __shared__ float t[32][33];
    int b = blockIdx.z;
    int p0 = blockIdx.x * 32, c0 = blockIdx.y * 32;
    int tx = threadIdx.x, ty = threadIdx.y;
#pragma unroll
    for (int j = 0; j < 32; j += 8)
        t[ty + j][tx] = x[((size_t)b * CIN + c0 + ty + j) * HW + p0 + tx];
    __syncthreads();
#pragma unroll
    for (int j = 0; j < 32; j += 8)
        g_xt[((size_t)b * HW + p0 + ty + j) * CIN + c0 + tx] = t[tx][ty + j];
}

// B-tile smem layout: Bs[s(4)][w(64)][8] with inner = (klocal&3)*2 + (klocal>>2)
// fragment read: v2 at Bs[s][nt*8 + (lane>>2)][(lane&3)*2]  (conflict-free)

// ---------------- K2: offset-conv GEMM, pipelined ---------------------------
__global__ __launch_bounds__(256, 2) void k_offgemm(const float* __restrict__ b_off) {
    __shared__ float As[2][2048];
    __shared__ float Bs[2][2048];
    const int tid = threadIdx.x, lane = tid & 31, wid = tid >> 5;
    const int b = blockIdx.x >> 6, h = blockIdx.x & 63;
    const int warp_m = wid & 1, warp_n = wid >> 1;
    const int wq = tid >> 2, q = tid & 3;

    float acc[2][2][4];
#pragma unroll
    for (int i = 0; i < 2; i++)
#pragma unroll
        for (int t = 0; t < 2; t++)
#pragma unroll
            for (int r = 0; r < 4; r++) acc[i][t][r] = 0.f;

    uint32_t as_sm[2];
    as_sm[0] = (uint32_t)__cvta_generic_to_shared(&As[0][0]);
    as_sm[1] = (uint32_t)__cvta_generic_to_shared(&As[1][0]);

    auto buildB = [&](int cc, int dst) {
        int k9 = cc >> 3, cb = (cc & 7) * 32;
        int gy = h + k9 / 3 - 1, gx = wq + k9 % 3 - 1;
        float4 v0 = make_float4(0, 0, 0, 0), v1 = v0;
        if (gy >= 0 && gy < Hdim && gx >= 0 && gx < Wdim) {
            const float4* src = (const float4*)(g_xt +
                ((size_t)(b * HW + gy * 64 + gx)) * 256 + cb + q * 8);
            v0 = tf4(src[0]); v1 = tf4(src[1]);
        }
        float* bs = &Bs[dst][0] + q * 512 + wq * 8;
        bs[0] = v0.x; bs[2] = v0.y; bs[4] = v0.z; bs[6] = v0.w;
        bs[1] = v1.x; bs[3] = v1.y; bs[5] = v1.z; bs[7] = v1.w;
    };
    auto loadA = [&](int cc, int dst) {
        const float4* src = (const float4*)(g_wofff + cc * 2048);
#pragma unroll
        for (int i = 0; i < 2; i++)
            CP_ASYNC16(as_sm[dst] + (tid + i * 256) * 16, src + tid + i * 256);
        CP_COMMIT();
    };

    loadA(0, 0);
    buildB(0, 0);

    for (int c = 0; c < NCHUNK; c++) {
        const int buf = c & 1;
        CP_WAIT0();
        __syncthreads();   // As[buf] visible; all readers of buf^1 are past it
        if (c + 1 < NCHUNK) {
            loadA(c + 1, buf ^ 1);     // safe: buf^1 readers finished at barrier
            buildB(c + 1, buf ^ 1);
        }
#pragma unroll
        for (int s = 0; s < 4; s++) {
            uint32_t af[2][4], bf[2][2];
#pragma unroll
            for (int i = 0; i < 2; i++) {
                const uint32_t* p = (const uint32_t*)&As[buf][((s * 4 + warp_m * 2 + i) * 32 + lane) * 4];
                af[i][0] = p[0]; af[i][1] = p[1]; af[i][2] = p[2]; af[i][3] = p[3];
            }
#pragma unroll
            for (int t = 0; t < 2; t++) {
                int nt = warp_n * 2 + t;
                const uint32_t* p = (const uint32_t*)&Bs[buf][(s * 512 + (nt * 8 + (lane >> 2)) * 8 + (lane & 3) * 2)];
                bf[t][0] = p[0]; bf[t][1] = p[1];
            }
#pragma unroll
            for (int i = 0; i < 2; i++)
#pragma unroll
                for (int t = 0; t < 2; t++)
                    mma_tf32(acc[i][t], af[i], bf[t]);
        }
    }
    // epilogue -> g_om2[ch][pos] (+b_off), ch<54
#pragma unroll
    for (int i = 0; i < 2; i++) {
        int ch0 = (warp_m * 2 + i) * 16 + (lane >> 2);
#pragma unroll
        for (int t = 0; t < 2; t++) {
            int wcol = (warp_n * 2 + t) * 8 + (lane & 3) * 2;
            int pos = b * HW + h * 64 + wcol;
            if (ch0 < 54) {
                float bv = b_off[ch0];
                *(float2*)&g_om2[(size_t)ch0 * NCOL + pos] =
                    make_float2(acc[i][t][0] + bv, acc[i][t][1] + bv);
            }
            if (ch0 + 8 < 54) {
                float bv = b_off[ch0 + 8];
                *(float2*)&g_om2[(size_t)(ch0 + 8) * NCOL + pos] =
                    make_float2(acc[i][t][2] + bv, acc[i][t][3] + bv);
            }
        }
    }
}

// ---------------- K3: offsets -> bilinear params ----------------------------
__global__ void k_params() {
    int i = blockIdx.x * blockDim.x + threadIdx.x;   // ((b*2+dg)*9+k)*HW + sp
    int sp = i & 4095;
    int t = i >> 12;
    int k = t % 9; t /= 9;
    int dg = t & 1, b = t >> 1;
    int h = sp >> 6, w = sp & 63;
    int pos = b * HW + sp;

    float oy = g_om2[(size_t)(dg * 18 + k) * NCOL + pos];
    float ox = g_om2[(size_t)(dg * 18 + 9 + k) * NCOL + pos];
    float mr = g_om2[(size_t)(36 + dg * 9 + k) * NCOL + pos];
    float m = 1.f / (1.f + expf(-mr));

    float py = oy + (float)(h + k / 3 - 1);
    float px = ox + (float)(w + k % 3 - 1);
    float y0f = floorf(py), x0f = floorf(px);
    float wy1 = py - y0f, wx1 = px - x0f;
    float wy0 = 1.f - wy1, wx0 = 1.f - wx1;
    int y0 = (int)y0f, x0 = (int)x0f;
    int y1 = y0 + 1, x1 = x0 + 1;
    float fy0 = (y0 >= 0 && y0 < Hdim) ? 1.f : 0.f;
    float fy1 = (y1 >= 0 && y1 < Hdim) ? 1.f : 0.f;
    float fx0 = (x0 >= 0 && x0 < Wdim) ? 1.f : 0.f;
    float fx1 = (x1 >= 0 && x1 < Wdim) ? 1.f : 0.f;
    int iy0 = min(max(y0, 0), Hdim - 1) * Wdim;
    int iy1 = min(max(y1, 0), Hdim - 1) * Wdim;
    int ix0 = min(max(x0, 0), Wdim - 1);
    int ix1 = min(max(x1, 0), Wdim - 1);

    g_pw[i] = make_float4(wy0 * wx0 * m * fy0 * fx0, wy0 * wx1 * m * fy0 * fx1,
                          wy1 * wx0 * m * fy1 * fx0, wy1 * wx1 * m * fy1 * fx1);
    g_pi[i] = make_int4(iy0 + ix0, iy0 + ix1, iy1 + ix0, iy1 + ix1);
}

// ---------------- K4: main GEMM (M=256), sampling fused, pipelined ----------
// dynamic smem: As 2x8192 floats (64KB) + Bs 2x2048 floats (16KB) = 80KB
__global__ __launch_bounds__(256, 2) void k_maingemm(const float* __restrict__ bias,
                                                     float* __restrict__ outp) {
    extern __shared__ float dsm[];
    float* Asb[2] = { dsm, dsm + 8192 };
    float* Bsb[2] = { dsm + 16384, dsm + 16384 + 2048 };
    const int tid = threadIdx.x, lane = tid & 31, wid = tid >> 5;
    const int b = blockIdx.x >> 6, h = blockIdx.x & 63;
    const int warp_m = wid & 3, warp_n = wid >> 2;
    const int wq = tid >> 2, q = tid & 3;

    float acc[4][4][4];
#pragma unroll
    for (int i = 0; i < 4; i++)
#pragma unroll
        for (int t = 0; t < 4; t++)
#pragma unroll
            for (int r = 0; r < 4; r++) acc[i][t][r] = 0.f;

    uint32_t as_sm[2];
    as_sm[0] = (uint32_t)__cvta_generic_to_shared(Asb[0]);
    as_sm[1] = (uint32_t)__cvta_generic_to_shared(Asb[1]);

    auto loadA = [&](int cc, int dst) {
        const float4* src = (const float4*)(g_wrf + (size_t)cc * 8192);
#pragma unroll
        for (int i = 0; i < 8; i++)
            CP_ASYNC16(as_sm[dst] + (tid + i * 256) * 16, src + tid + i * 256);
        CP_COMMIT();
    };
    auto buildB = [&](int cc, int dst) {
        int dg = cc / 36, km = (cc % 36) >> 2, cb = (cc & 3) * 32;
        int task = ((b * 2 + dg) * 9 + km) * HW + h * 64 + wq;
        float4 pw = g_pw[task];
        int4 pi = g_pi[task];
        const float* xb = g_xt + ((size_t)b * HW) * 256 + dg * 128 + cb + q * 8;
        const float4* s0 = (const float4*)(xb + (size_t)pi.x * 256);
        const float4* s1 = (const float4*)(xb + (size_t)pi.y * 256);
        const float4* s2 = (const float4*)(xb + (size_t)pi.z * 256);
        const float4* s3 = (const float4*)(xb + (size_t)pi.w * 256);
        float4 a0 = s0[0], b0 = s1[0], c0 = s2[0], d0 = s3[0];
        float4 a1 = s0[1], b1 = s1[1], c1 = s2[1], d1 = s3[1];
        float4 v0 = tf4(make_float4(
            pw.x * a0.x + pw.y * b0.x + pw.z * c0.x + pw.w * d0.x,
            pw.x * a0.y + pw.y * b0.y + pw.z * c0.y + pw.w * d0.y,
            pw.x * a0.z + pw.y * b0.z + pw.z * c0.z + pw.w * d0.z,
            pw.x * a0.w + pw.y * b0.w + pw.z * c0.w + pw.w * d0.w));
        float4 v1 = tf4(make_float4(
            pw.x * a1.x + pw.y * b1.x + pw.z * c1.x + pw.w * d1.x,
            pw.x * a1.y + pw.y * b1.y + pw.z * c1.y + pw.w * d1.y,
            pw.x * a1.z + pw.y * b1.z + pw.z * c1.z + pw.w * d1.z,
            pw.x * a1.w + pw.y * b1.w + pw.z * c1.w + pw.w * d1.w));
        float* bs = Bsb[dst] + q * 512 + wq * 8;
        bs[0] = v0.x; bs[2] = v0.y; bs[4] = v0.z; bs[6] = v0.w;
        bs[1] = v1.x; bs[3] = v1.y; bs[5] = v1.z; bs[7] = v1.w;
    };

    loadA(0, 0);
    buildB(0, 0);

    for (int c = 0; c < NCHUNK; c++) {
        const int buf = c & 1;
        CP_WAIT0();
        __syncthreads();   // As[buf] visible; all readers of buf^1 are past it
        if (c + 1 < NCHUNK) {
            loadA(c + 1, buf ^ 1);     // safe: buf^1 readers finished at barrier
            buildB(c + 1, buf ^ 1);
        }
#pragma unroll
        for (int s = 0; s < 4; s++) {
            uint32_t af[4][4], bf[4][2];
#pragma unroll
            for (int i = 0; i < 4; i++) {
                const uint32_t* p = (const uint32_t*)&Asb[buf][((s * 16 + warp_m * 4 + i) * 32 + lane) * 4];
                af[i][0] = p[0]; af[i][1] = p[1]; af[i][2] = p[2]; af[i][3] = p[3];
            }
#pragma unroll
            for (int t = 0; t < 4; t++) {
                int nt = warp_n * 4 + t;
                const uint32_t* p = (const uint32_t*)&Bsb[buf][(s * 512 + (nt * 8 + (lane >> 2)) * 8 + (lane & 3) * 2)];
                bf[t][0] = p[0]; bf[t][1] = p[1];
            }
#pragma unroll
            for (int i = 0; i < 4; i++)
#pragma unroll
                for (int t = 0; t < 4; t++)
                    mma_tf32(acc[i][t], af[i], bf[t]);
        }
    }
    // epilogue -> out[b][oc][h][w] (+bias)
#pragma unroll
    for (int i = 0; i < 4; i++) {
        int oc0 = (warp_m * 4 + i) * 16 + (lane >> 2);
        float bv0 = bias[oc0], bv8 = bias[oc0 + 8];
#pragma unroll
        for (int t = 0; t < 4; t++) {
            int wcol = (warp_n * 4 + t) * 8 + (lane & 3) * 2;
            size_t base = ((size_t)(b * 256 + oc0)) * HW + h * 64 + wcol;
            *(float2*)&outp[base] = make_float2(acc[i][t][0] + bv0, acc[i][t][1] + bv0);
            *(float2*)&outp[base + 8 * HW] = make_float2(acc[i][t][2] + bv8, acc[i][t][3] + bv8);
        }
    }
}

// ---------------- launch ----------------------------------------------------
extern "C" void kernel_launch(void* const* d_in, const int* in_sizes, int n_in,
                              void* d_out, int out_size) {
    const float* x      = (const float*)d_in[0];
    const float* w_off  = (const float*)d_in[1];
    const float* b_off  = (const float*)d_in[2];
    const float* weight = (const float*)d_in[3];
    const float* bias   = (const float*)d_in[4];
    float* out = (float*)d_out;

    const int MAIN_SMEM = (2 * 8192 + 2 * 2048) * 4;   // 80 KB
    cudaFuncSetAttribute(k_maingemm, cudaFuncAttributeMaxDynamicSharedMemorySize, MAIN_SMEM);

    k_repack<<<(NCHUNK * 8192 + 255) / 256, 256>>>(weight, w_off);
    k_transpose<<<dim3(HW / 32, CIN / 32, BATCH), dim3(32, 8)>>>(x);
    k_offgemm<<<256, 256>>>(b_off);
    k_params<<<BATCH * 2 * 9 * HW / 256, 256>>>();
    k_maingemm<<<256, 256, MAIN_SMEM>>>(bias, out);
}

// round 8
// speedup vs baseline: 2.3630x; 1.0401x over previous
#include <cuda_runtime.h>
#include <cstdint>

// DCNv2 forward on GB300 via mma.sync tf32, latency-hidden pipeline.
// B=4, Cin=Cout=256, H=W=64, DG=2, K=3x3. KTOT=2304, NCOL=16384.

#define BATCH 4
#define CIN   256
#define COUT  256
#define Hdim  64
#define Wdim  64
#define HW    4096
#define KTOT  2304
#define NCOL  16384
#define NCHUNK 72                 // K chunks of 32

// ---------------- device scratch (no cudaMalloc) ----------------------------
__device__ float  g_xt[BATCH * HW * CIN];     // x transposed [b][pos][c] 16 MB
__device__ float  g_wrf[NCHUNK * 8192];       // main A, fragment-packed
__device__ float  g_wofff[NCHUNK * 2048];     // offset A (M pad 64), frag-packed
__device__ float  g_om2[54 * NCOL];           // offset conv out [ch][pos]
__device__ float4 g_pw[BATCH * 2 * 9 * HW];   // bilinear weights (mask premul)
__device__ int4   g_pi[BATCH * 2 * 9 * HW];   // bilinear corner offsets

// ---------------- helpers ---------------------------------------------------
__device__ __forceinline__ float to_tf32(float f) {
    uint32_t b;
    asm("cvt.rna.tf32.f32 %0, %1;" : "=r"(b) : "f"(f));
    return __uint_as_float(b);
}
__device__ __forceinline__ void mma_tf32(float* d, const uint32_t* a, const uint32_t* b) {
    asm volatile(
        "mma.sync.aligned.m16n8k8.row.col.f32.tf32.tf32.f32 "
        "{%0,%1,%2,%3}, {%4,%5,%6,%7}, {%8,%9}, {%0,%1,%2,%3};"
        : "+f"(d[0]), "+f"(d[1]), "+f"(d[2]), "+f"(d[3])
        : "r"(a[0]), "r"(a[1]), "r"(a[2]), "r"(a[3]), "r"(b[0]), "r"(b[1]));
}
#define CP_ASYNC16(sa, gp) \
    asm volatile("cp.async.cg.shared.global [%0], [%1], 16;" :: "r"(sa), "l"(gp))
#define CP_COMMIT() asm volatile("cp.async.commit_group;" ::: "memory")
#define CP_WAIT0()  asm volatile("cp.async.wait_group 0;" ::: "memory")

// ---------------- K0: fragment-pack weights ---------------------------------
// A fragment (m16n8k8.tf32, row): a_r holds A[mt*16 + (lane>>2) + 8*(r&1)]
//                                  [klocal = (lane&3) + 4*(r>>1)]
__global__ void k_repack(const float* __restrict__ weight,
                         const float* __restrict__ w_off) {
    int i = blockIdx.x * blockDim.x + threadIdx.x;
    if (i < NCHUNK * 8192) {
        int c = i >> 13, r2 = i & 8191;
        int s = r2 >> 11, mt = (r2 >> 7) & 15, lane = (r2 >> 2) & 31, r = r2 & 3;
        int oc = mt * 16 + (lane >> 2) + 8 * (r & 1);
        int kk = c * 32 + s * 8 + (lane & 3) + 4 * (r >> 1);
        int dg = kk / 1152, km = (kk >> 7) % 9, cc = kk & 127;
        g_wrf[i] = to_tf32(weight[(oc * CIN + dg * 128 + cc) * 9 + km]);
    }
    if (i < NCHUNK * 2048) {
        int c = i >> 11, r2 = i & 2047;
        int s = r2 >> 9, mt = (r2 >> 7) & 3, lane = (r2 >> 2) & 31, r = r2 & 3;
        int oc = mt * 16 + (lane >> 2) + 8 * (r & 1);
        int kk = c * 32 + s * 8 + (lane & 3) + 4 * (r >> 1);
        int k9 = kk >> 8, cc = kk & 255;
        g_wofff[i] = (oc < 54) ? to_tf32(w_off[(oc * CIN + cc) * 9 + k9]) : 0.f;
    }
}

// ---------------- K1: transpose x -> [b][pos][c] ----------------------------
__global__ void k_transpose(const float* __restrict__ x) {
    __shared__ float t[32][33];
    int b = blockIdx.z;
    int p0 = blockIdx.x * 32, c0 = blockIdx.y * 32;
    int tx = threadIdx.x, ty = threadIdx.y;
#pragma unroll
    for (int j = 0; j < 32; j += 8)
        t[ty + j][tx] = x[((size_t)b * CIN + c0 + ty + j) * HW + p0 + tx];
    __syncthreads();
#pragma unroll
    for (int j = 0; j < 32; j += 8)
        g_xt[((size_t)b * HW + p0 + ty + j) * CIN + c0 + tx] = t[tx][ty + j];
}

// B-tile smem layout: Bs[s(4)][w(64)][8] with inner = (klocal&3)*2 + (klocal>>2)
// fragment read: v2 at Bs[s][nt*8 + (lane>>2)][(lane&3)*2]  (conflict-free)

// ---------------- K2: offset-conv GEMM, latency-hidden ----------------------
__global__ __launch_bounds__(256, 2) void k_offgemm(const float* __restrict__ b_off) {
    __shared__ float As[2][2048];
    __shared__ float Bs[2][2048];
    const int tid = threadIdx.x, lane = tid & 31, wid = tid >> 5;
    const int b = blockIdx.x >> 6, h = blockIdx.x & 63;
    const int warp_m = wid & 1, warp_n = wid >> 1;
    const int wq = tid >> 2, q = tid & 3;

    float acc[2][2][4];
#pragma unroll
    for (int i = 0; i < 2; i++)
#pragma unroll
        for (int t = 0; t < 2; t++)
#pragma unroll
            for (int r = 0; r < 4; r++) acc[i][t][r] = 0.f;

    uint32_t as_sm[2];
    as_sm[0] = (uint32_t)__cvta_generic_to_shared(&As[0][0]);
    as_sm[1] = (uint32_t)__cvta_generic_to_shared(&As[1][0]);

    float4 rv0, rv1;                       // raw gather regs (held across MMAs)
    auto gatherB = [&](int cc) {
        int k9 = cc >> 3, cb = (cc & 7) * 32;
        int gy = h + k9 / 3 - 1, gx = wq + k9 % 3 - 1;
        rv0 = make_float4(0, 0, 0, 0); rv1 = rv0;
        if (gy >= 0 && gy < Hdim && gx >= 0 && gx < Wdim) {
            const float4* src = (const float4*)(g_xt +
                ((size_t)(b * HW + gy * 64 + gx)) * 256 + cb + q * 8);
            rv0 = src[0]; rv1 = src[1];
        }
    };
    auto storeB = [&](int dst) {           // consume raw regs after MMA stage
        float* bs = &Bs[dst][0] + q * 512 + wq * 8;
        bs[0] = to_tf32(rv0.x); bs[2] = to_tf32(rv0.y);
        bs[4] = to_tf32(rv0.z); bs[6] = to_tf32(rv0.w);
        bs[1] = to_tf32(rv1.x); bs[3] = to_tf32(rv1.y);
        bs[5] = to_tf32(rv1.z); bs[7] = to_tf32(rv1.w);
    };
    auto loadA = [&](int cc, int dst) {
        const float4* src = (const float4*)(g_wofff + cc * 2048);
#pragma unroll
        for (int i = 0; i < 2; i++)
            CP_ASYNC16(as_sm[dst] + (tid + i * 256) * 16, src + tid + i * 256);
        CP_COMMIT();
    };

    // prologue
    gatherB(0); storeB(0); loadA(0, 0);

    for (int c = 0; c < NCHUNK; c++) {
        const int buf = c & 1;
        CP_WAIT0();
        __syncthreads();   // As/Bs[buf] visible; readers of buf^1 are done
        if (c + 1 < NCHUNK) {
            gatherB(c + 1);            // issue LDGs; consumed after MMAs
            loadA(c + 1, buf ^ 1);
        }
#pragma unroll
        for (int s = 0; s < 4; s++) {
            uint32_t af[2][4], bf[2][2];
#pragma unroll
            for (int i = 0; i < 2; i++) {
                const uint32_t* p = (const uint32_t*)&As[buf][((s * 4 + warp_m * 2 + i) * 32 + lane) * 4];
                af[i][0] = p[0]; af[i][1] = p[1]; af[i][2] = p[2]; af[i][3] = p[3];
            }
#pragma unroll
            for (int t = 0; t < 2; t++) {
                int nt = warp_n * 2 + t;
                const uint32_t* p = (const uint32_t*)&Bs[buf][(s * 512 + (nt * 8 + (lane >> 2)) * 8 + (lane & 3) * 2)];
                bf[t][0] = p[0]; bf[t][1] = p[1];
            }
#pragma unroll
            for (int i = 0; i < 2; i++)
#pragma unroll
                for (int t = 0; t < 2; t++)
                    mma_tf32(acc[i][t], af[i], bf[t]);
        }
        if (c + 1 < NCHUNK) storeB(buf ^ 1);
    }
    // epilogue -> g_om2[ch][pos] (+b_off), ch<54
#pragma unroll
    for (int i = 0; i < 2; i++) {
        int ch0 = (warp_m * 2 + i) * 16 + (lane >> 2);
#pragma unroll
        for (int t = 0; t < 2; t++) {
            int wcol = (warp_n * 2 + t) * 8 + (lane & 3) * 2;
            int pos = b * HW + h * 64 + wcol;
            if (ch0 < 54) {
                float bv = b_off[ch0];
                *(float2*)&g_om2[(size_t)ch0 * NCOL + pos] =
                    make_float2(acc[i][t][0] + bv, acc[i][t][1] + bv);
            }
            if (ch0 + 8 < 54) {
                float bv = b_off[ch0 + 8];
                *(float2*)&g_om2[(size_t)(ch0 + 8) * NCOL + pos] =
                    make_float2(acc[i][t][2] + bv, acc[i][t][3] + bv);
            }
        }
    }
}

// ---------------- K3: offsets -> bilinear params ----------------------------
__global__ void k_params() {
    int i = blockIdx.x * blockDim.x + threadIdx.x;   // ((b*2+dg)*9+k)*HW + sp
    int sp = i & 4095;
    int t = i >> 12;
    int k = t % 9; t /= 9;
    int dg = t & 1, b = t >> 1;
    int h = sp >> 6, w = sp & 63;
    int pos = b * HW + sp;

    float oy = g_om2[(size_t)(dg * 18 + k) * NCOL + pos];
    float ox = g_om2[(size_t)(dg * 18 + 9 + k) * NCOL + pos];
    float mr = g_om2[(size_t)(36 + dg * 9 + k) * NCOL + pos];
    float m = 1.f / (1.f + expf(-mr));

    float py = oy + (float)(h + k / 3 - 1);
    float px = ox + (float)(w + k % 3 - 1);
    float y0f = floorf(py), x0f = floorf(px);
    float wy1 = py - y0f, wx1 = px - x0f;
    float wy0 = 1.f - wy1, wx0 = 1.f - wx1;
    int y0 = (int)y0f, x0 = (int)x0f;
    int y1 = y0 + 1, x1 = x0 + 1;
    float fy0 = (y0 >= 0 && y0 < Hdim) ? 1.f : 0.f;
    float fy1 = (y1 >= 0 && y1 < Hdim) ? 1.f : 0.f;
    float fx0 = (x0 >= 0 && x0 < Wdim) ? 1.f : 0.f;
    float fx1 = (x1 >= 0 && x1 < Wdim) ? 1.f : 0.f;
    int iy0 = min(max(y0, 0), Hdim - 1) * Wdim;
    int iy1 = min(max(y1, 0), Hdim - 1) * Wdim;
    int ix0 = min(max(x0, 0), Wdim - 1);
    int ix1 = min(max(x1, 0), Wdim - 1);

    g_pw[i] = make_float4(wy0 * wx0 * m * fy0 * fx0, wy0 * wx1 * m * fy0 * fx1,
                          wy1 * wx0 * m * fy1 * fx0, wy1 * wx1 * m * fy1 * fx1);
    g_pi[i] = make_int4(iy0 + ix0, iy0 + ix1, iy1 + ix0, iy1 + ix1);
}

// ---------------- K4: main GEMM (M=256), sampling fused, latency-hidden -----
// dynamic smem floats: As 2x8192 | Bs 2x2048 | pwS 4608 | piS(ushort4) 2304eq
#define SM_AS   0
#define SM_BS   16384
#define SM_PW   20480
#define SM_PI   25088
#define SM_TOT  27392     // floats -> 109568 bytes
__global__ __launch_bounds__(256, 2) void k_maingemm(const float* __restrict__ bias,
                                                     float* __restrict__ outp) {
    extern __shared__ float dsm[];
    float* Asb[2] = { dsm + SM_AS, dsm + SM_AS + 8192 };
    float* Bsb[2] = { dsm + SM_BS, dsm + SM_BS + 2048 };
    float4*  pwS = (float4*)(dsm + SM_PW);
    ushort4* piS = (ushort4*)(dsm + SM_PI);
    const int tid = threadIdx.x, lane = tid & 31, wid = tid >> 5;
    const int b = blockIdx.x >> 6, h = blockIdx.x & 63;
    const int warp_m = wid & 3, warp_n = wid >> 2;
    const int wq = tid >> 2, q = tid & 3;

    // preload this CTA's 18 (dg,km) param rows: 1152 entries
    for (int i = tid; i < 1152; i += 256) {
        int t = i >> 6, posw = i & 63;          // t = dg*9+km
        int dg = t / 9, km = t % 9;
        int gidx = ((b * 2 + dg) * 9 + km) * HW + h * 64 + posw;
        pwS[i] = g_pw[gidx];
        int4 p = g_pi[gidx];
        piS[i] = make_ushort4((unsigned short)p.x, (unsigned short)p.y,
                              (unsigned short)p.z, (unsigned short)p.w);
    }

    float acc[4][4][4];
#pragma unroll
    for (int i = 0; i < 4; i++)
#pragma unroll
        for (int t = 0; t < 4; t++)
#pragma unroll
            for (int r = 0; r < 4; r++) acc[i][t][r] = 0.f;

    uint32_t as_sm[2];
    as_sm[0] = (uint32_t)__cvta_generic_to_shared(Asb[0]);
    as_sm[1] = (uint32_t)__cvta_generic_to_shared(Asb[1]);

    auto loadA = [&](int cc, int dst) {
        const float4* src = (const float4*)(g_wrf + (size_t)cc * 8192);
#pragma unroll
        for (int i = 0; i < 8; i++)
            CP_ASYNC16(as_sm[dst] + (tid + i * 256) * 16, src + tid + i * 256);
        CP_COMMIT();
    };

    float4 ra0, ra1, rb0, rb1, rc0, rc1, rd0, rd1, rpw;  // raw gathers + weights
    auto gatherB = [&](int cc) {           // params via LDS, raw data via LDG
        int grp = cc >> 2, cb = (cc & 3) * 32;
        int dg = grp / 9;
        int pidx = grp * 64 + wq;
        rpw = pwS[pidx];
        ushort4 pi = piS[pidx];
        const float* xb = g_xt + ((size_t)b * HW) * 256 + dg * 128 + cb + q * 8;
        const float4* s0 = (const float4*)(xb + (size_t)pi.x * 256);
        const float4* s1 = (const float4*)(xb + (size_t)pi.y * 256);
        const float4* s2 = (const float4*)(xb + (size_t)pi.z * 256);
        const float4* s3 = (const float4*)(xb + (size_t)pi.w * 256);
        ra0 = s0[0]; ra1 = s0[1];
        rb0 = s1[0]; rb1 = s1[1];
        rc0 = s2[0]; rc1 = s2[1];
        rd0 = s3[0]; rd1 = s3[1];
    };
    auto storeB = [&](int dst) {           // combine + round + STS (post-MMA)
        float4 v0 = make_float4(
            rpw.x * ra0.x + rpw.y * rb0.x + rpw.z * rc0.x + rpw.w * rd0.x,
            rpw.x * ra0.y + rpw.y * rb0.y + rpw.z * rc0.y + rpw.w * rd0.y,
            rpw.x * ra0.z + rpw.y * rb0.z + rpw.z * rc0.z + rpw.w * rd0.z,
            rpw.x * ra0.w + rpw.y * rb0.w + rpw.z * rc0.w + rpw.w * rd0.w);
        float4 v1 = make_float4(
            rpw.x * ra1.x + rpw.y * rb1.x + rpw.z * rc1.x + rpw.w * rd1.x,
            rpw.x * ra1.y + rpw.y * rb1.y + rpw.z * rc1.y + rpw.w * rd1.y,
            rpw.x * ra1.z + rpw.y * rb1.z + rpw.z * rc1.z + rpw.w * rd1.z,
            rpw.x * ra1.w + rpw.y * rb1.w + rpw.z * rc1.w + rpw.w * rd1.w);
        float* bs = Bsb[dst] + q * 512 + wq * 8;
        bs[0] = to_tf32(v0.x); bs[2] = to_tf32(v0.y);
        bs[4] = to_tf32(v0.z); bs[6] = to_tf32(v0.w);
        bs[1] = to_tf32(v1.x); bs[3] = to_tf32(v1.y);
        bs[5] = to_tf32(v1.z); bs[7] = to_tf32(v1.w);
    };

    __syncthreads();                       // param table ready
    gatherB(0); storeB(0); loadA(0, 0);    // prologue (one exposed stall)

    for (int c = 0; c < NCHUNK; c++) {
        const int buf = c & 1;
        CP_WAIT0();
        __syncthreads();   // As/Bs[buf] visible; readers of buf^1 are done
        if (c + 1 < NCHUNK) {
            gatherB(c + 1);            // issue LDGs; consumed after MMAs
            loadA(c + 1, buf ^ 1);
        }
#pragma unroll
        for (int s = 0; s < 4; s++) {
            uint32_t af[4][4], bf[4][2];
#pragma unroll
            for (int i = 0; i < 4; i++) {
                const uint32_t* p = (const uint32_t*)&Asb[buf][((s * 16 + warp_m * 4 + i) * 32 + lane) * 4];
                af[i][0] = p[0]; af[i][1] = p[1]; af[i][2] = p[2]; af[i][3] = p[3];
            }
#pragma unroll
            for (int t = 0; t < 4; t++) {
                int nt = warp_n * 4 + t;
                const uint32_t* p = (const uint32_t*)&Bsb[buf][(s * 512 + (nt * 8 + (lane >> 2)) * 8 + (lane & 3) * 2)];
                bf[t][0] = p[0]; bf[t][1] = p[1];
            }
#pragma unroll
            for (int i = 0; i < 4; i++)
#pragma unroll
                for (int t = 0; t < 4; t++)
                    mma_tf32(acc[i][t], af[i], bf[t]);
        }
        if (c + 1 < NCHUNK) storeB(buf ^ 1);
    }
    // epilogue -> out[b][oc][h][w] (+bias)
#pragma unroll
    for (int i = 0; i < 4; i++) {
        int oc0 = (warp_m * 4 + i) * 16 + (lane >> 2);
        float bv0 = bias[oc0], bv8 = bias[oc0 + 8];
#pragma unroll
        for (int t = 0; t < 4; t++) {
            int wcol = (warp_n * 4 + t) * 8 + (lane & 3) * 2;
            size_t base = ((size_t)(b * 256 + oc0)) * HW + h * 64 + wcol;
            *(float2*)&outp[base] = make_float2(acc[i][t][0] + bv0, acc[i][t][1] + bv0);
            *(float2*)&outp[base + 8 * HW] = make_float2(acc[i][t][2] + bv8, acc[i][t][3] + bv8);
        }
    }
}

// ---------------- launch ----------------------------------------------------
extern "C" void kernel_launch(void* const* d_in, const int* in_sizes, int n_in,
                              void* d_out, int out_size) {
    const float* x      = (const float*)d_in[0];
    const float* w_off  = (const float*)d_in[1];
    const float* b_off  = (const float*)d_in[2];
    const float* weight = (const float*)d_in[3];
    const float* bias   = (const float*)d_in[4];
    float* out = (float*)d_out;

    const int MAIN_SMEM = SM_TOT * 4;      // 109568 bytes
    cudaFuncSetAttribute(k_maingemm, cudaFuncAttributeMaxDynamicSharedMemorySize, MAIN_SMEM);

    k_repack<<<(NCHUNK * 8192 + 255) / 256, 256>>>(weight, w_off);
    k_transpose<<<dim3(HW / 32, CIN / 32, BATCH), dim3(32, 8)>>>(x);
    k_offgemm<<<256, 256>>>(b_off);
    k_params<<<BATCH * 2 * 9 * HW / 256, 256>>>();
    k_maingemm<<<256, 256, MAIN_SMEM>>>(bias, out);
}

// round 10
// speedup vs baseline: 5.1205x; 2.1670x over previous
#include <cuda_runtime.h>
#include <cuda_fp16.h>
#include <cstdint>

// DCNv2 forward on GB300 via mma.sync fp16 (m16n8k16), latency-hidden pipeline.
// B=4, Cin=Cout=256, H=W=64, DG=2, K=3x3. KTOT=2304, NCOL=16384.

#define BATCH 4
#define CIN   256
#define COUT  256
#define Hdim  64
#define Wdim  64
#define HW    4096
#define KTOT  2304
#define NCOL  16384
#define NCHUNK 72                 // K chunks of 32

// ---------------- device scratch (no cudaMalloc) ----------------------------
__device__ float    g_xt[BATCH * HW * CIN];   // x transposed [b][pos][c] 16 MB
__device__ uint32_t g_wrf[NCHUNK * 4096];     // main A fp16 frag-packed (16KB/chunk)
__device__ uint32_t g_wofff[NCHUNK * 1024];   // offset A fp16 frag-packed (4KB/chunk)
__device__ float    g_om2[54 * NCOL];         // offset conv out [ch][pos]
__device__ float4   g_pw[BATCH * 2 * 9 * HW]; // bilinear weights (mask premul)
__device__ int4     g_pi[BATCH * 2 * 9 * HW]; // bilinear corner offsets

// ---------------- helpers ---------------------------------------------------
__device__ __forceinline__ void mma_fp16(float* d, const uint32_t* a, const uint32_t* b) {
    asm volatile(
        "mma.sync.aligned.m16n8k16.row.col.f32.f16.f16.f32 "
        "{%0,%1,%2,%3}, {%4,%5,%6,%7}, {%8,%9}, {%0,%1,%2,%3};"
        : "+f"(d[0]), "+f"(d[1]), "+f"(d[2]), "+f"(d[3])
        : "r"(a[0]), "r"(a[1]), "r"(a[2]), "r"(a[3]), "r"(b[0]), "r"(b[1]));
}
__device__ __forceinline__ uint32_t pack_h2(float f0, float f1) {
    __half2 h = __floats2half2_rn(f0, f1);
    return *(const uint32_t*)&h;
}
#define CP_ASYNC16(sa, gp) \
    asm volatile("cp.async.cg.shared.global [%0], [%1], 16;" :: "r"(sa), "l"(gp))
#define CP_COMMIT() asm volatile("cp.async.commit_group;" ::: "memory")
#define CP_WAIT0()  asm volatile("cp.async.wait_group 0;" ::: "memory")

// ---------------- K0: fragment-pack weights (fp16, m16n8k16 layout) ---------
// reg r of thread lane in m-tile mt, k-step s:
//   row = mt*16 + (lane>>2) + 8*(r&1)
//   k   = s*16 + (lane&3)*2 + 8*(r>>1)  (half2 = k, k+1)
__global__ void k_repack(const float* __restrict__ weight,
                         const float* __restrict__ w_off) {
    int i = blockIdx.x * blockDim.x + threadIdx.x;
    if (i < NCHUNK * 4096) {
        int c = i >> 12, r2 = i & 4095;
        int s = r2 >> 11, mt = (r2 >> 7) & 15, lane = (r2 >> 2) & 31, r = r2 & 3;
        int row = mt * 16 + (lane >> 2) + 8 * (r & 1);
        int kk = c * 32 + s * 16 + (lane & 3) * 2 + 8 * (r >> 1);
        float f0, f1;
        {
            int dg = kk / 1152, km = (kk >> 7) % 9, cc = kk & 127;
            f0 = weight[(row * CIN + dg * 128 + cc) * 9 + km];
        }
        {
            int kk1 = kk + 1;
            int dg = kk1 / 1152, km = (kk1 >> 7) % 9, cc = kk1 & 127;
            f1 = weight[(row * CIN + dg * 128 + cc) * 9 + km];
        }
        g_wrf[i] = pack_h2(f0, f1);
    }
    if (i < NCHUNK * 1024) {
        int c = i >> 10, r2 = i & 1023;
        int s = r2 >> 9, mt = (r2 >> 7) & 3, lane = (r2 >> 2) & 31, r = r2 & 3;
        int row = mt * 16 + (lane >> 2) + 8 * (r & 1);
        int kk = c * 32 + s * 16 + (lane & 3) * 2 + 8 * (r >> 1);
        float f0 = 0.f, f1 = 0.f;
        if (row < 54) {
            int k9 = kk >> 8, cc = kk & 255;
            f0 = w_off[(row * CIN + cc) * 9 + k9];
            int kk1 = kk + 1, k91 = kk1 >> 8, cc1 = kk1 & 255;
            f1 = w_off[(row * CIN + cc1) * 9 + k91];
        }
        g_wofff[i] = pack_h2(f0, f1);
    }
}

// ---------------- K1: transpose x -> [b][pos][c] ----------------------------
__global__ void k_transpose(const float* __restrict__ x) {
    __shared__ float t[32][33];
    int b = blockIdx.z;
    int p0 = blockIdx.x * 32, c0 = blockIdx.y * 32;
    int tx = threadIdx.x, ty = threadIdx.y;
#pragma unroll
    for (int j = 0; j < 32; j += 8)
        t[ty + j][tx] = x[((size_t)b * CIN + c0 + ty + j) * HW + p0 + tx];
    __syncthreads();
#pragma unroll
    for (int j = 0; j < 32; j += 8)
        g_xt[((size_t)b * HW + p0 + ty + j) * CIN + c0 + tx] = t[tx][ty + j];
}

// B smem layout (per buffer): halves[(s*64 + col)*16 + ks], s=k-step(2), ks=k%16.
// Thread (wq=tid>>2, q=tid&3) owns chunk-channels q*8..q*8+7 of col wq:
//   s = q>>1, ks = (q&1)*8 + j  -> 8 contiguous halves = one STS.128.
// Frag read (col, t=lane&3): b0b1 = b32 at halves (s*64+col)*16 + t*2;
//                            b2b3 = +8 halves (16B).

// ---------------- K2: offset-conv GEMM (fp16), latency-hidden ---------------
__global__ __launch_bounds__(256, 2) void k_offgemm(const float* __restrict__ b_off) {
    __shared__ uint32_t As[2][1024];     // 4KB per buffer
    __shared__ __half  Bs[2][2048];      // 4KB per buffer
    const int tid = threadIdx.x, lane = tid & 31, wid = tid >> 5;
    const int b = blockIdx.x >> 6, h = blockIdx.x & 63;
    const int warp_m = wid & 1, warp_n = wid >> 1;
    const int wq = tid >> 2, q = tid & 3;

    float acc[2][2][4];
#pragma unroll
    for (int i = 0; i < 2; i++)
#pragma unroll
        for (int t = 0; t < 2; t++)
#pragma unroll
            for (int r = 0; r < 4; r++) acc[i][t][r] = 0.f;

    uint32_t as_sm[2];
    as_sm[0] = (uint32_t)__cvta_generic_to_shared(&As[0][0]);
    as_sm[1] = (uint32_t)__cvta_generic_to_shared(&As[1][0]);

    float4 rv0, rv1;
    auto gatherB = [&](int cc) {
        int k9 = cc >> 3, cb = (cc & 7) * 32;
        int gy = h + k9 / 3 - 1, gx = wq + k9 % 3 - 1;
        rv0 = make_float4(0, 0, 0, 0); rv1 = rv0;
        if (gy >= 0 && gy < Hdim && gx >= 0 && gx < Wdim) {
            const float4* src = (const float4*)(g_xt +
                ((size_t)(b * HW + gy * 64 + gx)) * 256 + cb + q * 8);
            rv0 = src[0]; rv1 = src[1];
        }
    };
    auto storeB = [&](int dst) {
        uint4 v = make_uint4(pack_h2(rv0.x, rv0.y), pack_h2(rv0.z, rv0.w),
                             pack_h2(rv1.x, rv1.y), pack_h2(rv1.z, rv1.w));
        *(uint4*)&Bs[dst][((q >> 1) * 64 + wq) * 16 + (q & 1) * 8] = v;
    };
    auto loadA = [&](int cc, int dst) {
        const uint4* src = (const uint4*)(g_wofff + cc * 1024);
        CP_ASYNC16(as_sm[dst] + tid * 16, src + tid);
        CP_COMMIT();
    };

    gatherB(0); storeB(0); loadA(0, 0);

    for (int c = 0; c < NCHUNK; c++) {
        const int buf = c & 1;
        CP_WAIT0();
        __syncthreads();
        if (c + 1 < NCHUNK) {
            gatherB(c + 1);
            loadA(c + 1, buf ^ 1);
        }
#pragma unroll
        for (int s = 0; s < 2; s++) {
            uint32_t af[2][4], bf[2][2];
#pragma unroll
            for (int i = 0; i < 2; i++) {
                const uint4* p = (const uint4*)&As[buf][((s * 4 + warp_m * 2 + i) * 32 + lane) * 4];
                uint4 v = *p;
                af[i][0] = v.x; af[i][1] = v.y; af[i][2] = v.z; af[i][3] = v.w;
            }
#pragma unroll
            for (int t = 0; t < 2; t++) {
                int col = (warp_n * 2 + t) * 8 + (lane >> 2);
                const __half* base = &Bs[buf][(s * 64 + col) * 16 + (lane & 3) * 2];
                bf[t][0] = *(const uint32_t*)base;
                bf[t][1] = *(const uint32_t*)(base + 8);
            }
#pragma unroll
            for (int i = 0; i < 2; i++)
#pragma unroll
                for (int t = 0; t < 2; t++)
                    mma_fp16(acc[i][t], af[i], bf[t]);
        }
        if (c + 1 < NCHUNK) storeB(buf ^ 1);
    }
    // epilogue -> g_om2[ch][pos] (+b_off), ch<54
#pragma unroll
    for (int i = 0; i < 2; i++) {
        int ch0 = (warp_m * 2 + i) * 16 + (lane >> 2);
#pragma unroll
        for (int t = 0; t < 2; t++) {
            int wcol = (warp_n * 2 + t) * 8 + (lane & 3) * 2;
            int pos = b * HW + h * 64 + wcol;
            if (ch0 < 54) {
                float bv = b_off[ch0];
                *(float2*)&g_om2[(size_t)ch0 * NCOL + pos] =
                    make_float2(acc[i][t][0] + bv, acc[i][t][1] + bv);
            }
            if (ch0 + 8 < 54) {
                float bv = b_off[ch0 + 8];
                *(float2*)&g_om2[(size_t)(ch0 + 8) * NCOL + pos] =
                    make_float2(acc[i][t][2] + bv, acc[i][t][3] + bv);
            }
        }
    }
}

// ---------------- K3: offsets -> bilinear params ----------------------------
__global__ void k_params() {
    int i = blockIdx.x * blockDim.x + threadIdx.x;   // ((b*2+dg)*9+k)*HW + sp
    int sp = i & 4095;
    int t = i >> 12;
    int k = t % 9; t /= 9;
    int dg = t & 1, b = t >> 1;
    int h = sp >> 6, w = sp & 63;
    int pos = b * HW + sp;

    float oy = g_om2[(size_t)(dg * 18 + k) * NCOL + pos];
    float ox = g_om2[(size_t)(dg * 18 + 9 + k) * NCOL + pos];
    float mr = g_om2[(size_t)(36 + dg * 9 + k) * NCOL + pos];
    float m = 1.f / (1.f + expf(-mr));

    float py = oy + (float)(h + k / 3 - 1);
    float px = ox + (float)(w + k % 3 - 1);
    float y0f = floorf(py), x0f = floorf(px);
    float wy1 = py - y0f, wx1 = px - x0f;
    float wy0 = 1.f - wy1, wx0 = 1.f - wx1;
    int y0 = (int)y0f, x0 = (int)x0f;
    int y1 = y0 + 1, x1 = x0 + 1;
    float fy0 = (y0 >= 0 && y0 < Hdim) ? 1.f : 0.f;
    float fy1 = (y1 >= 0 && y1 < Hdim) ? 1.f : 0.f;
    float fx0 = (x0 >= 0 && x0 < Wdim) ? 1.f : 0.f;
    float fx1 = (x1 >= 0 && x1 < Wdim) ? 1.f : 0.f;
    int iy0 = min(max(y0, 0), Hdim - 1) * Wdim;
    int iy1 = min(max(y1, 0), Hdim - 1) * Wdim;
    int ix0 = min(max(x0, 0), Wdim - 1);
    int ix1 = min(max(x1, 0), Wdim - 1);

    g_pw[i] = make_float4(wy0 * wx0 * m * fy0 * fx0, wy0 * wx1 * m * fy0 * fx1,
                          wy1 * wx0 * m * fy1 * fx0, wy1 * wx1 * m * fy1 * fx1);
    g_pi[i] = make_int4(iy0 + ix0, iy0 + ix1, iy1 + ix0, iy1 + ix1);
}

// ---------------- K4: main GEMM (fp16, M=256), sampling fused ---------------
// dynamic smem bytes: As 2x16384 | Bs 2x4096 | pw 18432 | pi 9216 = 68608
#define SMB_AS  0
#define SMB_BS  32768
#define SMB_PW  40960
#define SMB_PI  59392
#define SMB_TOT 68608
__global__ __launch_bounds__(256, 2) void k_maingemm(const float* __restrict__ bias,
                                                     float* __restrict__ outp) {
    extern __shared__ __align__(16) char dsm[];
    uint32_t* AsU[2] = { (uint32_t*)(dsm + SMB_AS), (uint32_t*)(dsm + SMB_AS + 16384) };
    __half*   BsH[2] = { (__half*)(dsm + SMB_BS), (__half*)(dsm + SMB_BS + 4096) };
    float4*  pwS = (float4*)(dsm + SMB_PW);
    ushort4* piS = (ushort4*)(dsm + SMB_PI);
    const int tid = threadIdx.x, lane = tid & 31, wid = tid >> 5;
    const int b = blockIdx.x >> 6, h = blockIdx.x & 63;
    const int warp_m = wid & 3, warp_n = wid >> 2;
    const int wq = tid >> 2, q = tid & 3;

    // preload this CTA's 18 (dg,km) param rows: 1152 entries
    for (int i = tid; i < 1152; i += 256) {
        int t = i >> 6, posw = i & 63;          // t = dg*9+km
        int dg = t / 9, km = t % 9;
        int gidx = ((b * 2 + dg) * 9 + km) * HW + h * 64 + posw;
        pwS[i] = g_pw[gidx];
        int4 p = g_pi[gidx];
        piS[i] = make_ushort4((unsigned short)p.x, (unsigned short)p.y,
                              (unsigned short)p.z, (unsigned short)p.w);
    }

    float acc[4][4][4];
#pragma unroll
    for (int i = 0; i < 4; i++)
#pragma unroll
        for (int t = 0; t < 4; t++)
#pragma unroll
            for (int r = 0; r < 4; r++) acc[i][t][r] = 0.f;

    uint32_t as_sm[2];
    as_sm[0] = (uint32_t)__cvta_generic_to_shared(AsU[0]);
    as_sm[1] = (uint32_t)__cvta_generic_to_shared(AsU[1]);

    auto loadA = [&](int cc, int dst) {
        const uint4* src = (const uint4*)(g_wrf + (size_t)cc * 4096);
#pragma unroll
        for (int i = 0; i < 4; i++)
            CP_ASYNC16(as_sm[dst] + (tid + i * 256) * 16, src + tid + i * 256);
        CP_COMMIT();
    };

    float4 ra0, ra1, rb0, rb1, rc0, rc1, rd0, rd1, rpw;
    auto gatherB = [&](int cc) {
        int grp = cc >> 2, cb = (cc & 3) * 32;
        int dg = grp / 9;
        int pidx = grp * 64 + wq;
        rpw = pwS[pidx];
        ushort4 pi = piS[pidx];
        const float* xb = g_xt + ((size_t)b * HW) * 256 + dg * 128 + cb + q * 8;
        const float4* s0 = (const float4*)(xb + (size_t)pi.x * 256);
        const float4* s1 = (const float4*)(xb + (size_t)pi.y * 256);
        const float4* s2 = (const float4*)(xb + (size_t)pi.z * 256);
        const float4* s3 = (const float4*)(xb + (size_t)pi.w * 256);
        ra0 = s0[0]; ra1 = s0[1];
        rb0 = s1[0]; rb1 = s1[1];
        rc0 = s2[0]; rc1 = s2[1];
        rd0 = s3[0]; rd1 = s3[1];
    };
    auto storeB = [&](int dst) {
        float4 v0 = make_float4(
            rpw.x * ra0.x + rpw.y * rb0.x + rpw.z * rc0.x + rpw.w * rd0.x,
            rpw.x * ra0.y + rpw.y * rb0.y + rpw.z * rc0.y + rpw.w * rd0.y,
            rpw.x * ra0.z + rpw.y * rb0.z + rpw.z * rc0.z + rpw.w * rd0.z,
            rpw.x * ra0.w + rpw.y * rb0.w + rpw.z * rc0.w + rpw.w * rd0.w);
        float4 v1 = make_float4(
            rpw.x * ra1.x + rpw.y * rb1.x + rpw.z * rc1.x + rpw.w * rd1.x,
            rpw.x * ra1.y + rpw.y * rb1.y + rpw.z * rc1.y + rpw.w * rd1.y,
            rpw.x * ra1.z + rpw.y * rb1.z + rpw.z * rc1.z + rpw.w * rd1.z,
            rpw.x * ra1.w + rpw.y * rb1.w + rpw.z * rc1.w + rpw.w * rd1.w);
        uint4 v = make_uint4(pack_h2(v0.x, v0.y), pack_h2(v0.z, v0.w),
                             pack_h2(v1.x, v1.y), pack_h2(v1.z, v1.w));
        *(uint4*)&BsH[dst][((q >> 1) * 64 + wq) * 16 + (q & 1) * 8] = v;
    };

    __syncthreads();                       // param table ready
    gatherB(0); storeB(0); loadA(0, 0);

    for (int c = 0; c < NCHUNK; c++) {
        const int buf = c & 1;
        CP_WAIT0();
        __syncthreads();
        if (c + 1 < NCHUNK) {
            gatherB(c + 1);
            loadA(c + 1, buf ^ 1);
        }
#pragma unroll
        for (int s = 0; s < 2; s++) {
            uint32_t af[4][4], bf[4][2];
#pragma unroll
            for (int i = 0; i < 4; i++) {
                const uint4* p = (const uint4*)&AsU[buf][((s * 16 + warp_m * 4 + i) * 32 + lane) * 4];
                uint4 v = *p;
                af[i][0] = v.x; af[i][1] = v.y; af[i][2] = v.z; af[i][3] = v.w;
            }
#pragma unroll
            for (int t = 0; t < 4; t++) {
                int col = (warp_n * 4 + t) * 8 + (lane >> 2);
                const __half* base = &BsH[buf][(s * 64 + col) * 16 + (lane & 3) * 2];
                bf[t][0] = *(const uint32_t*)base;
                bf[t][1] = *(const uint32_t*)(base + 8);
            }
#pragma unroll
            for (int i = 0; i < 4; i++)
#pragma unroll
                for (int t = 0; t < 4; t++)
                    mma_fp16(acc[i][t], af[i], bf[t]);
        }
        if (c + 1 < NCHUNK) storeB(buf ^ 1);
    }
    // epilogue -> out[b][oc][h][w] (+bias)
#pragma unroll
    for (int i = 0; i < 4; i++) {
        int oc0 = (warp_m * 4 + i) * 16 + (lane >> 2);
        float bv0 = bias[oc0], bv8 = bias[oc0 + 8];
#pragma unroll
        for (int t = 0; t < 4; t++) {
            int wcol = (warp_n * 4 + t) * 8 + (lane & 3) * 2;
            size_t base = ((size_t)(b * 256 + oc0)) * HW + h * 64 + wcol;
            *(float2*)&outp[base] = make_float2(acc[i][t][0] + bv0, acc[i][t][1] + bv0);
            *(float2*)&outp[base + 8 * HW] = make_float2(acc[i][t][2] + bv8, acc[i][t][3] + bv8);
        }
    }
}

// ---------------- launch ----------------------------------------------------
extern "C" void kernel_launch(void* const* d_in, const int* in_sizes, int n_in,
                              void* d_out, int out_size) {
    const float* x      = (const float*)d_in[0];
    const float* w_off  = (const float*)d_in[1];
    const float* b_off  = (const float*)d_in[2];
    const float* weight = (const float*)d_in[3];
    const float* bias   = (const float*)d_in[4];
    float* out = (float*)d_out;

    cudaFuncSetAttribute(k_maingemm, cudaFuncAttributeMaxDynamicSharedMemorySize, SMB_TOT);

    k_repack<<<(NCHUNK * 4096 + 255) / 256, 256>>>(weight, w_off);
    k_transpose<<<dim3(HW / 32, CIN / 32, BATCH), dim3(32, 8)>>>(x);
    k_offgemm<<<256, 256>>>(b_off);
    k_params<<<BATCH * 2 * 9 * HW / 256, 256>>>();
    k_maingemm<<<256, 256, SMB_TOT>>>(bias, out);
}

// round 11
// speedup vs baseline: 6.5640x; 1.2819x over previous
#include <cuda_runtime.h>
#include <cuda_fp16.h>
#include <cstdint>

// DCNv2 forward on GB300: fp16 mma.sync m16n8k16, fp16 x, ldmatrix B-frags.
// B=4, Cin=Cout=256, H=W=64, DG=2, K=3x3. KTOT=2304, NCOL=16384.

#define BATCH 4
#define CIN   256
#define COUT  256
#define Hdim  64
#define Wdim  64
#define HW    4096
#define KTOT  2304
#define NCOL  16384
#define NCHUNK 72                 // K chunks of 32

// ---------------- device scratch (no cudaMalloc) ----------------------------
__device__ __half   g_xth[BATCH * HW * CIN];  // x transposed fp16 [b][pos][c] 8MB
__device__ uint32_t g_wrf[NCHUNK * 4096];     // main A fp16 frag-packed
__device__ uint32_t g_wofff[NCHUNK * 1024];   // offset A fp16 frag-packed
__device__ float    g_om2[54 * NCOL];         // offset conv out [ch][pos]
__device__ float4   g_pw[BATCH * 2 * 9 * HW]; // bilinear weights (mask premul)
__device__ int4     g_pi[BATCH * 2 * 9 * HW]; // bilinear corner offsets

// ---------------- helpers ---------------------------------------------------
__device__ __forceinline__ void mma_fp16(float* d, const uint32_t* a, const uint32_t* b) {
    asm volatile(
        "mma.sync.aligned.m16n8k16.row.col.f32.f16.f16.f32 "
        "{%0,%1,%2,%3}, {%4,%5,%6,%7}, {%8,%9}, {%0,%1,%2,%3};"
        : "+f"(d[0]), "+f"(d[1]), "+f"(d[2]), "+f"(d[3])
        : "r"(a[0]), "r"(a[1]), "r"(a[2]), "r"(a[3]), "r"(b[0]), "r"(b[1]));
}
__device__ __forceinline__ uint32_t pack_h2(float f0, float f1) {
    __half2 h = __floats2half2_rn(f0, f1);
    return *(const uint32_t*)&h;
}
#define LDSM_X4(r0, r1, r2, r3, a) \
    asm volatile("ldmatrix.sync.aligned.m8n8.x4.shared.b16 {%0,%1,%2,%3}, [%4];" \
                 : "=r"(r0), "=r"(r1), "=r"(r2), "=r"(r3) : "r"(a))
#define CP_ASYNC16(sa, gp) \
    asm volatile("cp.async.cg.shared.global [%0], [%1], 16;" :: "r"(sa), "l"(gp))
#define CP_COMMIT() asm volatile("cp.async.commit_group;" ::: "memory")
#define CP_WAIT0()  asm volatile("cp.async.wait_group 0;" ::: "memory")

// ---------------- K0: fragment-pack weights (fp16, m16n8k16 layout) ---------
__global__ void k_repack(const float* __restrict__ weight,
                         const float* __restrict__ w_off) {
    int i = blockIdx.x * blockDim.x + threadIdx.x;
    if (i < NCHUNK * 4096) {
        int c = i >> 12, r2 = i & 4095;
        int s = r2 >> 11, mt = (r2 >> 7) & 15, lane = (r2 >> 2) & 31, r = r2 & 3;
        int row = mt * 16 + (lane >> 2) + 8 * (r & 1);
        int kk = c * 32 + s * 16 + (lane & 3) * 2 + 8 * (r >> 1);
        float f0, f1;
        {
            int dg = kk / 1152, km = (kk >> 7) % 9, cc = kk & 127;
            f0 = weight[(row * CIN + dg * 128 + cc) * 9 + km];
        }
        {
            int kk1 = kk + 1;
            int dg = kk1 / 1152, km = (kk1 >> 7) % 9, cc = kk1 & 127;
            f1 = weight[(row * CIN + dg * 128 + cc) * 9 + km];
        }
        g_wrf[i] = pack_h2(f0, f1);
    }
    if (i < NCHUNK * 1024) {
        int c = i >> 10, r2 = i & 1023;
        int s = r2 >> 9, mt = (r2 >> 7) & 3, lane = (r2 >> 2) & 31, r = r2 & 3;
        int row = mt * 16 + (lane >> 2) + 8 * (r & 1);
        int kk = c * 32 + s * 16 + (lane & 3) * 2 + 8 * (r >> 1);
        float f0 = 0.f, f1 = 0.f;
        if (row < 54) {
            int k9 = kk >> 8, cc = kk & 255;
            f0 = w_off[(row * CIN + cc) * 9 + k9];
            int kk1 = kk + 1, k91 = kk1 >> 8, cc1 = kk1 & 255;
            f1 = w_off[(row * CIN + cc1) * 9 + k91];
        }
        g_wofff[i] = pack_h2(f0, f1);
    }
}

// ---------------- K1: transpose x -> fp16 [b][pos][c] -----------------------
__global__ void k_transpose(const float* __restrict__ x) {
    __shared__ float t[32][33];
    int b = blockIdx.z;
    int p0 = blockIdx.x * 32, c0 = blockIdx.y * 32;
    int tx = threadIdx.x, ty = threadIdx.y;
#pragma unroll
    for (int j = 0; j < 32; j += 8)
        t[ty + j][tx] = x[((size_t)b * CIN + c0 + ty + j) * HW + p0 + tx];
    __syncthreads();
#pragma unroll
    for (int j = 0; j < 32; j += 8)
        g_xth[((size_t)b * HW + p0 + ty + j) * CIN + c0 + tx] = __float2half(t[tx][ty + j]);
}

// ---------------- K2: offset-conv GEMM (fp16), latency-hidden ---------------
// B smem: halves[(s*64+col)*16 + ks]; thread (wq,q) stores ch q*8.. as 16B.
__global__ __launch_bounds__(256, 2) void k_offgemm(const float* __restrict__ b_off) {
    __shared__ uint32_t As[2][1024];     // 4KB per buffer
    __shared__ __align__(16) __half Bs[2][2048];
    const int tid = threadIdx.x, lane = tid & 31, wid = tid >> 5;
    const int b = blockIdx.x >> 6, h = blockIdx.x & 63;
    const int warp_m = wid & 1, warp_n = wid >> 1;
    const int wq = tid >> 2, q = tid & 3;

    float acc[2][2][4];
#pragma unroll
    for (int i = 0; i < 2; i++)
#pragma unroll
        for (int t = 0; t < 2; t++)
#pragma unroll
            for (int r = 0; r < 4; r++) acc[i][t][r] = 0.f;

    uint32_t as_sm[2];
    as_sm[0] = (uint32_t)__cvta_generic_to_shared(&As[0][0]);
    as_sm[1] = (uint32_t)__cvta_generic_to_shared(&As[1][0]);

    uint4 rv;
    auto gatherB = [&](int cc) {
        int k9 = cc >> 3, cb = (cc & 7) * 32;
        int gy = h + k9 / 3 - 1, gx = wq + k9 % 3 - 1;
        rv = make_uint4(0, 0, 0, 0);
        if (gy >= 0 && gy < Hdim && gx >= 0 && gx < Wdim)
            rv = *(const uint4*)(g_xth + ((size_t)(b * HW + gy * 64 + gx)) * 256 + cb + q * 8);
    };
    auto storeB = [&](int dst) {
        *(uint4*)&Bs[dst][((q >> 1) * 64 + wq) * 16 + (q & 1) * 8] = rv;
    };
    auto loadA = [&](int cc, int dst) {
        const uint4* src = (const uint4*)(g_wofff + cc * 1024);
        CP_ASYNC16(as_sm[dst] + tid * 16, src + tid);
        CP_COMMIT();
    };

    gatherB(0); storeB(0); loadA(0, 0);

    for (int c = 0; c < NCHUNK; c++) {
        const int buf = c & 1;
        CP_WAIT0();
        __syncthreads();
        if (c + 1 < NCHUNK) {
            gatherB(c + 1);
            loadA(c + 1, buf ^ 1);
        }
#pragma unroll
        for (int s = 0; s < 2; s++) {
            uint32_t af[2][4], bf[2][2];
#pragma unroll
            for (int i = 0; i < 2; i++) {
                const uint4* p = (const uint4*)&As[buf][((s * 4 + warp_m * 2 + i) * 32 + lane) * 4];
                uint4 v = *p;
                af[i][0] = v.x; af[i][1] = v.y; af[i][2] = v.z; af[i][3] = v.w;
            }
#pragma unroll
            for (int t = 0; t < 2; t++) {
                int col = (warp_n * 2 + t) * 8 + (lane >> 2);
                const __half* base = &Bs[buf][(s * 64 + col) * 16 + (lane & 3) * 2];
                bf[t][0] = *(const uint32_t*)base;
                bf[t][1] = *(const uint32_t*)(base + 8);
            }
#pragma unroll
            for (int i = 0; i < 2; i++)
#pragma unroll
                for (int t = 0; t < 2; t++)
                    mma_fp16(acc[i][t], af[i], bf[t]);
        }
        if (c + 1 < NCHUNK) storeB(buf ^ 1);
    }
#pragma unroll
    for (int i = 0; i < 2; i++) {
        int ch0 = (warp_m * 2 + i) * 16 + (lane >> 2);
#pragma unroll
        for (int t = 0; t < 2; t++) {
            int wcol = (warp_n * 2 + t) * 8 + (lane & 3) * 2;
            int pos = b * HW + h * 64 + wcol;
            if (ch0 < 54) {
                float bv = b_off[ch0];
                *(float2*)&g_om2[(size_t)ch0 * NCOL + pos] =
                    make_float2(acc[i][t][0] + bv, acc[i][t][1] + bv);
            }
            if (ch0 + 8 < 54) {
                float bv = b_off[ch0 + 8];
                *(float2*)&g_om2[(size_t)(ch0 + 8) * NCOL + pos] =
                    make_float2(acc[i][t][2] + bv, acc[i][t][3] + bv);
            }
        }
    }
}

// ---------------- K3: offsets -> bilinear params ----------------------------
__global__ void k_params() {
    int i = blockIdx.x * blockDim.x + threadIdx.x;
    int sp = i & 4095;
    int t = i >> 12;
    int k = t % 9; t /= 9;
    int dg = t & 1, b = t >> 1;
    int h = sp >> 6, w = sp & 63;
    int pos = b * HW + sp;

    float oy = g_om2[(size_t)(dg * 18 + k) * NCOL + pos];
    float ox = g_om2[(size_t)(dg * 18 + 9 + k) * NCOL + pos];
    float mr = g_om2[(size_t)(36 + dg * 9 + k) * NCOL + pos];
    float m = 1.f / (1.f + expf(-mr));

    float py = oy + (float)(h + k / 3 - 1);
    float px = ox + (float)(w + k % 3 - 1);
    float y0f = floorf(py), x0f = floorf(px);
    float wy1 = py - y0f, wx1 = px - x0f;
    float wy0 = 1.f - wy1, wx0 = 1.f - wx1;
    int y0 = (int)y0f, x0 = (int)x0f;
    int y1 = y0 + 1, x1 = x0 + 1;
    float fy0 = (y0 >= 0 && y0 < Hdim) ? 1.f : 0.f;
    float fy1 = (y1 >= 0 && y1 < Hdim) ? 1.f : 0.f;
    float fx0 = (x0 >= 0 && x0 < Wdim) ? 1.f : 0.f;
    float fx1 = (x1 >= 0 && x1 < Wdim) ? 1.f : 0.f;
    int iy0 = min(max(y0, 0), Hdim - 1) * Wdim;
    int iy1 = min(max(y1, 0), Hdim - 1) * Wdim;
    int ix0 = min(max(x0, 0), Wdim - 1);
    int ix1 = min(max(x1, 0), Wdim - 1);

    g_pw[i] = make_float4(wy0 * wx0 * m * fy0 * fx0, wy0 * wx1 * m * fy0 * fx1,
                          wy1 * wx0 * m * fy1 * fx0, wy1 * wx1 * m * fy1 * fx1);
    g_pi[i] = make_int4(iy0 + ix0, iy0 + ix1, iy1 + ix0, iy1 + ix1);
}

// ---------------- K4: main GEMM (fp16, M=256), sampling fused ---------------
// B smem: halves[(s*64+col)*24 + khalf*8 + j]  (48B col stride, conflict-free
// for ldmatrix: 12*r mod 32 all distinct). 128*24 halves = 6144B per buffer.
#define SMB_AS  0
#define SMB_BS  32768
#define BS_BUF  6144
#define SMB_PW  45056
#define SMB_PI  63488
#define SMB_TOT 72704
__global__ __launch_bounds__(256, 2) void k_maingemm(const float* __restrict__ bias,
                                                     float* __restrict__ outp) {
    extern __shared__ __align__(16) char dsm[];
    uint32_t* AsU[2] = { (uint32_t*)(dsm + SMB_AS), (uint32_t*)(dsm + SMB_AS + 16384) };
    __half*   BsH[2] = { (__half*)(dsm + SMB_BS), (__half*)(dsm + SMB_BS + BS_BUF) };
    float4*  pwS = (float4*)(dsm + SMB_PW);
    ushort4* piS = (ushort4*)(dsm + SMB_PI);
    const int tid = threadIdx.x, lane = tid & 31, wid = tid >> 5;
    const int b = blockIdx.x >> 6, h = blockIdx.x & 63;
    const int warp_m = wid & 3, warp_n = wid >> 2;
    const int wq = tid >> 2, q = tid & 3;

    for (int i = tid; i < 1152; i += 256) {
        int t = i >> 6, posw = i & 63;          // t = dg*9+km
        int dg = t / 9, km = t % 9;
        int gidx = ((b * 2 + dg) * 9 + km) * HW + h * 64 + posw;
        pwS[i] = g_pw[gidx];
        int4 p = g_pi[gidx];
        piS[i] = make_ushort4((unsigned short)p.x, (unsigned short)p.y,
                              (unsigned short)p.z, (unsigned short)p.w);
    }

    float acc[4][4][4];
#pragma unroll
    for (int i = 0; i < 4; i++)
#pragma unroll
        for (int t = 0; t < 4; t++)
#pragma unroll
            for (int r = 0; r < 4; r++) acc[i][t][r] = 0.f;

    uint32_t as_sm[2];
    as_sm[0] = (uint32_t)__cvta_generic_to_shared(AsU[0]);
    as_sm[1] = (uint32_t)__cvta_generic_to_shared(AsU[1]);

    // ldmatrix lane addresses: seg = lane>>3 selects (tile-within-pair, khalf)
    uint32_t lmaddr[2][2];
    {
        int seg = lane >> 3, row = lane & 7;
        int tsel = seg >> 1, khalf = seg & 1;
        uint32_t bs0 = (uint32_t)__cvta_generic_to_shared(BsH[0]);
#pragma unroll
        for (int s = 0; s < 2; s++)
#pragma unroll
            for (int p = 0; p < 2; p++) {
                int col = (warp_n * 4 + p * 2 + tsel) * 8 + row;
                lmaddr[s][p] = bs0 + ((s * 64 + col) * 24 + khalf * 8) * 2;
            }
    }

    auto loadA = [&](int cc, int dst) {
        const uint4* src = (const uint4*)(g_wrf + (size_t)cc * 4096);
#pragma unroll
        for (int i = 0; i < 4; i++)
            CP_ASYNC16(as_sm[dst] + (tid + i * 256) * 16, src + tid + i * 256);
        CP_COMMIT();
    };

    uint4 ga, gb, gc, gd; float4 rpw;
    auto gatherB = [&](int cc) {
        int grp = cc >> 2, cb = (cc & 3) * 32;
        int dg = grp / 9;
        int pidx = grp * 64 + wq;
        rpw = pwS[pidx];
        ushort4 pi = piS[pidx];
        const __half* xb = g_xth + ((size_t)b * HW) * 256 + dg * 128 + cb + q * 8;
        ga = *(const uint4*)(xb + (size_t)pi.x * 256);
        gb = *(const uint4*)(xb + (size_t)pi.y * 256);
        gc = *(const uint4*)(xb + (size_t)pi.z * 256);
        gd = *(const uint4*)(xb + (size_t)pi.w * 256);
    };
    auto storeB = [&](int dst) {
        const __half2* ha = (const __half2*)&ga;
        const __half2* hb = (const __half2*)&gb;
        const __half2* hc = (const __half2*)&gc;
        const __half2* hd = (const __half2*)&gd;
        uint32_t o[4];
#pragma unroll
        for (int j = 0; j < 4; j++) {
            float2 a = __half22float2(ha[j]);
            float2 bb = __half22float2(hb[j]);
            float2 cc2 = __half22float2(hc[j]);
            float2 dd = __half22float2(hd[j]);
            float vx = rpw.x * a.x + rpw.y * bb.x + rpw.z * cc2.x + rpw.w * dd.x;
            float vy = rpw.x * a.y + rpw.y * bb.y + rpw.z * cc2.y + rpw.w * dd.y;
            o[j] = pack_h2(vx, vy);
        }
        *(uint4*)&BsH[dst][((q >> 1) * 64 + wq) * 24 + (q & 1) * 8] =
            make_uint4(o[0], o[1], o[2], o[3]);
    };

    __syncthreads();                       // param table ready
    gatherB(0); storeB(0); loadA(0, 0);

    for (int c = 0; c < NCHUNK; c++) {
        const int buf = c & 1;
        const uint32_t boff = buf * BS_BUF;
        CP_WAIT0();
        __syncthreads();
        if (c + 1 < NCHUNK) {
            gatherB(c + 1);
            loadA(c + 1, buf ^ 1);
        }
#pragma unroll
        for (int s = 0; s < 2; s++) {
            uint32_t af[4][4], bf[4][2];
#pragma unroll
            for (int i = 0; i < 4; i++) {
                const uint4* p = (const uint4*)&AsU[buf][((s * 16 + warp_m * 4 + i) * 32 + lane) * 4];
                uint4 v = *p;
                af[i][0] = v.x; af[i][1] = v.y; af[i][2] = v.z; af[i][3] = v.w;
            }
#pragma unroll
            for (int p = 0; p < 2; p++) {
                uint32_t r0, r1, r2, r3;
                LDSM_X4(r0, r1, r2, r3, lmaddr[s][p] + boff);
                bf[p * 2][0] = r0; bf[p * 2][1] = r1;
                bf[p * 2 + 1][0] = r2; bf[p * 2 + 1][1] = r3;
            }
#pragma unroll
            for (int i = 0; i < 4; i++)
#pragma unroll
                for (int t = 0; t < 4; t++)
                    mma_fp16(acc[i][t], af[i], bf[t]);
        }
        if (c + 1 < NCHUNK) storeB(buf ^ 1);
    }
    // epilogue -> out[b][oc][h][w] (+bias)
#pragma unroll
    for (int i = 0; i < 4; i++) {
        int oc0 = (warp_m * 4 + i) * 16 + (lane >> 2);
        float bv0 = bias[oc0], bv8 = bias[oc0 + 8];
#pragma unroll
        for (int t = 0; t < 4; t++) {
            int wcol = (warp_n * 4 + t) * 8 + (lane & 3) * 2;
            size_t base = ((size_t)(b * 256 + oc0)) * HW + h * 64 + wcol;
            *(float2*)&outp[base] = make_float2(acc[i][t][0] + bv0, acc[i][t][1] + bv0);
            *(float2*)&outp[base + 8 * HW] = make_float2(acc[i][t][2] + bv8, acc[i][t][3] + bv8);
        }
    }
}

// ---------------- launch ----------------------------------------------------
extern "C" void kernel_launch(void* const* d_in, const int* in_sizes, int n_in,
                              void* d_out, int out_size) {
    const float* x      = (const float*)d_in[0];
    const float* w_off  = (const float*)d_in[1];
    const float* b_off  = (const float*)d_in[2];
    const float* weight = (const float*)d_in[3];
    const float* bias   = (const float*)d_in[4];
    float* out = (float*)d_out;

    cudaFuncSetAttribute(k_maingemm, cudaFuncAttributeMaxDynamicSharedMemorySize, SMB_TOT);

    k_repack<<<(NCHUNK * 4096 + 255) / 256, 256>>>(weight, w_off);
    k_transpose<<<dim3(HW / 32, CIN / 32, BATCH), dim3(32, 8)>>>(x);
    k_offgemm<<<256, 256>>>(b_off);
    k_params<<<BATCH * 2 * 9 * HW / 256, 256>>>();
    k_maingemm<<<256, 256, SMB_TOT>>>(bias, out);
}